// round 3
// baseline (speedup 1.0000x reference)
#include <cuda_runtime.h>
#include <cstdint>

// Problem constants
#define TOK   16384        // B*S tokens
#define HDIM  1024
#define FDIM  4096
#define NEXP  8

// GEMM tiling
#define BM 128
#define BN 128
#define BK 32
#define AST 36             // A smem row stride (BK + 4): frag banks = laneid (conflict-free)
#define BST 136            // B smem row stride (BN + 8): frag banks = 8*tg + gid (conflict-free)

// ---------------- scratch (device globals; no runtime allocation) ----------------
__device__ float g_xn[(size_t)TOK * HDIM];          //  67 MB  normalized input (fp32, tf32-roundable)
__device__ float g_h[(size_t)TOK * 2 * FDIM];       // 537 MB  relu(xn@W1+b1)-relu(b1), compact per-expert rows
__device__ float g_y[(size_t)TOK * 2 * HDIM];       // 134 MB  s_k * (h @ W2), indexed by (t*2+k)
__device__ float g_ctotal[HDIM];
__device__ float g_score[TOK * 2];
__device__ float g_stot[TOK];
__device__ int   g_cnt[NEXP];
__device__ int   g_off[NEXP];
__device__ int   g_elist[NEXP * TOK];               // entries = t*2+k

// ---------------- helpers ----------------
__device__ __forceinline__ float to_tf32(float x) {
    unsigned u;
    asm("cvt.rna.tf32.f32 %0, %1;" : "=r"(u) : "f"(x));
    return __uint_as_float(u);
}

__device__ __forceinline__ void mma_tf32(float (&d)[4], const unsigned (&a)[4], const unsigned (&b)[2]) {
    asm volatile(
        "mma.sync.aligned.m16n8k8.row.col.f32.tf32.tf32.f32 "
        "{%0,%1,%2,%3}, {%4,%5,%6,%7}, {%8,%9}, {%0,%1,%2,%3};"
        : "+f"(d[0]), "+f"(d[1]), "+f"(d[2]), "+f"(d[3])
        : "r"(a[0]), "r"(a[1]), "r"(a[2]), "r"(a[3]), "r"(b[0]), "r"(b[1]));
}

// ---------------- kernel 0: zero counters + c_total accumulator ----------------
__global__ void zero_kernel() {
    int i = threadIdx.x;             // blockDim = 1024
    if (i < NEXP) g_cnt[i] = 0;
    g_ctotal[i] = 0.f;
}

// ---------------- kernel 1: c_total[h] = sum_e relu(b1_e)@W2_e + sum_e b2_e ----------------
__global__ void ctotal_kernel(const float* __restrict__ W2,
                              const float* __restrict__ b1,
                              const float* __restrict__ b2) {
    int h = blockIdx.x * 256 + threadIdx.x;          // grid.x = 4
    int chunk = blockIdx.y;                           // grid.y = 64, 512 (e,f) pairs each
    float acc = 0.f;
    for (int i = 0; i < 512; i++) {
        int ef = chunk * 512 + i;                     // ef = e*FDIM + f
        float bb = b1[ef];
        if (bb > 0.f) acc += bb * W2[(size_t)ef * HDIM + h];
    }
    if (acc != 0.f) atomicAdd(&g_ctotal[h], acc);
    if (chunk < NEXP) atomicAdd(&g_ctotal[h], b2[chunk * HDIM + h]);
}

// ---------------- kernel 2: LayerNorm + router (softmax over 8, top-2) ----------------
__global__ void __launch_bounds__(256) ln_router_kernel(const float* __restrict__ x,
                                                        const float* __restrict__ gamma,
                                                        const float* __restrict__ beta,
                                                        const float* __restrict__ Wr,
                                                        const float* __restrict__ br) {
    const int t = blockIdx.x;
    const int tid = threadIdx.x;
    const int lane = tid & 31, wid = tid >> 5;

    const float4 xv = ((const float4*)(x + (size_t)t * HDIM))[tid];
    float s1 = xv.x + xv.y + xv.z + xv.w;
    float s2 = xv.x*xv.x + xv.y*xv.y + xv.z*xv.z + xv.w*xv.w;
    #pragma unroll
    for (int o = 16; o; o >>= 1) {
        s1 += __shfl_xor_sync(0xffffffffu, s1, o);
        s2 += __shfl_xor_sync(0xffffffffu, s2, o);
    }
    __shared__ float rs1[8], rs2[8];
    __shared__ float s_mu, s_rs;
    if (lane == 0) { rs1[wid] = s1; rs2[wid] = s2; }
    __syncthreads();
    if (wid == 0) {
        float a = (lane < 8) ? rs1[lane] : 0.f;
        float b = (lane < 8) ? rs2[lane] : 0.f;
        #pragma unroll
        for (int o = 4; o; o >>= 1) {
            a += __shfl_xor_sync(0xffffffffu, a, o);
            b += __shfl_xor_sync(0xffffffffu, b, o);
        }
        if (lane == 0) {
            float mu = a * (1.f / HDIM);
            float var = b * (1.f / HDIM) - mu * mu;
            s_mu = mu;
            s_rs = rsqrtf(var + 1e-5f);
        }
    }
    __syncthreads();
    const float mu = s_mu, rs = s_rs;

    const float4 g  = ((const float4*)gamma)[tid];
    const float4 be = ((const float4*)beta)[tid];
    float4 xn;
    xn.x = (xv.x - mu) * rs * g.x + be.x;
    xn.y = (xv.y - mu) * rs * g.y + be.y;
    xn.z = (xv.z - mu) * rs * g.z + be.z;
    xn.w = (xv.w - mu) * rs * g.w + be.w;
    ((float4*)(g_xn + (size_t)t * HDIM))[tid] = xn;

    // router logits: xn @ Wr   (Wr is [H, E] row-major)
    float lg[NEXP];
    #pragma unroll
    for (int e = 0; e < NEXP; e++) lg[e] = 0.f;
    const int h0 = tid * 4;
    const float xns[4] = {xn.x, xn.y, xn.z, xn.w};
    #pragma unroll
    for (int j = 0; j < 4; j++) {
        const float4 w0 = ((const float4*)(Wr + (size_t)(h0 + j) * NEXP))[0];
        const float4 w1 = ((const float4*)(Wr + (size_t)(h0 + j) * NEXP))[1];
        lg[0] += xns[j] * w0.x; lg[1] += xns[j] * w0.y;
        lg[2] += xns[j] * w0.z; lg[3] += xns[j] * w0.w;
        lg[4] += xns[j] * w1.x; lg[5] += xns[j] * w1.y;
        lg[6] += xns[j] * w1.z; lg[7] += xns[j] * w1.w;
    }
    #pragma unroll
    for (int e = 0; e < NEXP; e++)
        #pragma unroll
        for (int o = 16; o; o >>= 1)
            lg[e] += __shfl_xor_sync(0xffffffffu, lg[e], o);

    __shared__ float lred[8][NEXP];
    if (lane == 0)
        #pragma unroll
        for (int e = 0; e < NEXP; e++) lred[wid][e] = lg[e];
    __syncthreads();

    if (tid == 0) {
        float L[NEXP];
        #pragma unroll
        for (int e = 0; e < NEXP; e++) {
            L[e] = br[e];
            #pragma unroll
            for (int w = 0; w < 8; w++) L[e] += lred[w][e];
        }
        float mx = L[0];
        #pragma unroll
        for (int e = 1; e < NEXP; e++) mx = fmaxf(mx, L[e]);
        float ex[NEXP], den = 0.f;
        #pragma unroll
        for (int e = 0; e < NEXP; e++) { ex[e] = __expf(L[e] - mx); den += ex[e]; }
        int i0 = 0;
        #pragma unroll
        for (int e = 1; e < NEXP; e++) if (L[e] > L[i0]) i0 = e;
        int i1 = (i0 == 0) ? 1 : 0;
        #pragma unroll
        for (int e = 0; e < NEXP; e++) if (e != i0 && L[e] > L[i1]) i1 = e;
        float inv = 1.f / den;
        float sc0 = ex[i0] * inv, sc1 = ex[i1] * inv;
        g_score[2 * t]     = sc0;
        g_score[2 * t + 1] = sc1;
        g_stot[t] = sc0 + sc1;
        int p0 = atomicAdd(&g_cnt[i0], 1);
        g_elist[i0 * TOK + p0] = 2 * t;
        int p1 = atomicAdd(&g_cnt[i1], 1);
        g_elist[i1 * TOK + p1] = 2 * t + 1;
    }
}

// ---------------- kernel 3: exclusive scan of counts (E=8) ----------------
__global__ void offsets_kernel() {
    if (threadIdx.x == 0) {
        int s = 0;
        #pragma unroll
        for (int e = 0; e < NEXP; e++) { g_off[e] = s; s += g_cnt[e]; }
    }
}

// ---------------- GEMM (tf32 mma.sync), MODE 1: h = relu(xn@W1+b1)-relu(b1); MODE 2: y = s*(h@W2) ----------------
template <int MODE>
__global__ void __launch_bounds__(256, 1) gemm_kernel(const float* __restrict__ Bglob,
                                                      const float* __restrict__ bias) {
    constexpr int KDIM = (MODE == 1) ? HDIM : FDIM;
    constexpr int LDB  = (MODE == 1) ? FDIM : HDIM;
    constexpr int NDIM = (MODE == 1) ? FDIM : HDIM;
    constexpr int NKT  = KDIM / BK;

    const int e = blockIdx.z;
    const int cnt = g_cnt[e];
    const int mbase = blockIdx.y * BM;
    if (mbase >= cnt) return;
    const int nb = blockIdx.x * BN;
    const int off = g_off[e];

    extern __shared__ float sm[];
    float* As = sm;                          // 2 * BM * AST
    float* Bs = sm + 2 * BM * AST;           // 2 * BK * BST
    __shared__ int   s_rowoff[BM];
    __shared__ int   s_ent[BM];
    __shared__ float s_sc[BM];

    const int tid = threadIdx.x;
    if (tid < BM) {
        int r = mbase + tid;
        int rc = (r < cnt) ? r : (cnt - 1);
        int ent = g_elist[e * TOK + rc];
        if (MODE == 1) {
            s_rowoff[tid] = (ent >> 1) * HDIM;
        } else {
            s_rowoff[tid] = (off + rc) * FDIM;
            s_ent[tid] = ent;
            s_sc[tid]  = g_score[ent];
        }
    }
    __syncthreads();

    const float* Ag = (MODE == 1) ? g_xn : g_h;
    const float* Bptr = Bglob + (size_t)e * KDIM * NDIM + nb;

    const int arow = tid >> 3;               // 0..31 (+32/pass)
    const int acol = (tid & 7) * 4;
    const int bcol = (tid & 31) * 4;
    const int brow = tid >> 5;               // 0..7 (+8/pass)

    const int warp = tid >> 5, lane = tid & 31;
    const int wm = warp >> 2, wn = warp & 3; // warp tile 64 x 32
    const int gid = lane >> 2, tg = lane & 3;

    float acc[4][4][4];
    #pragma unroll
    for (int i = 0; i < 4; i++)
        #pragma unroll
        for (int j = 0; j < 4; j++)
            #pragma unroll
            for (int c = 0; c < 4; c++) acc[i][j][c] = 0.f;

    float4 ra[4], rb[4];

    auto load_g = [&](int k0) {
        #pragma unroll
        for (int p = 0; p < 4; p++) {
            int r = arow + p * 32;
            ra[p] = *(const float4*)(Ag + (size_t)s_rowoff[r] + k0 + acol);
            int kk = brow + p * 8;
            rb[p] = *(const float4*)(Bptr + (size_t)(k0 + kk) * LDB + bcol);
        }
    };
    auto store_s = [&](int buf) {
        float* A  = As + buf * BM * AST;
        float* Bb = Bs + buf * BK * BST;
        #pragma unroll
        for (int p = 0; p < 4; p++) {
            int r = arow + p * 32;
            float4 av = make_float4(to_tf32(ra[p].x), to_tf32(ra[p].y), to_tf32(ra[p].z), to_tf32(ra[p].w));
            *(float4*)(A + r * AST + acol) = av;
            int kk = brow + p * 8;
            float4 bv = make_float4(to_tf32(rb[p].x), to_tf32(rb[p].y), to_tf32(rb[p].z), to_tf32(rb[p].w));
            *(float4*)(Bb + kk * BST + bcol) = bv;
        }
    };
    auto compute = [&](int buf) {
        const float* A  = As + buf * BM * AST;
        const float* Bb = Bs + buf * BK * BST;
        #pragma unroll
        for (int ks = 0; ks < 4; ks++) {
            const int kb = ks * 8;
            unsigned af[4][4];
            #pragma unroll
            for (int mt = 0; mt < 4; mt++) {
                const float* ap = A + (wm * 64 + mt * 16 + gid) * AST + kb + tg;
                af[mt][0] = __float_as_uint(ap[0]);
                af[mt][2] = __float_as_uint(ap[4]);
                af[mt][1] = __float_as_uint(ap[8 * AST]);
                af[mt][3] = __float_as_uint(ap[8 * AST + 4]);
            }
            unsigned bf[4][2];
            #pragma unroll
            for (int nt = 0; nt < 4; nt++) {
                const int c = wn * 32 + nt * 8 + gid;
                bf[nt][0] = __float_as_uint(Bb[(kb + tg) * BST + c]);
                bf[nt][1] = __float_as_uint(Bb[(kb + tg + 4) * BST + c]);
            }
            #pragma unroll
            for (int mt = 0; mt < 4; mt++)
                #pragma unroll
                for (int nt = 0; nt < 4; nt++)
                    mma_tf32(acc[mt][nt], af[mt], bf[nt]);
        }
    };

    load_g(0);
    store_s(0);
    __syncthreads();
    for (int kt = 0; kt < NKT; kt++) {
        if (kt + 1 < NKT) load_g((kt + 1) * BK);
        compute(kt & 1);
        if (kt + 1 < NKT) store_s((kt + 1) & 1);
        __syncthreads();
    }

    // epilogue
    #pragma unroll
    for (int mt = 0; mt < 4; mt++) {
        #pragma unroll
        for (int pr = 0; pr < 2; pr++) {
            const int r = wm * 64 + mt * 16 + gid + pr * 8;
            if (mbase + r >= cnt) continue;
            #pragma unroll
            for (int nt = 0; nt < 4; nt++) {
                const int c  = wn * 32 + nt * 8 + 2 * tg;
                const int cg = nb + c;
                float v0 = acc[mt][nt][pr * 2 + 0];
                float v1 = acc[mt][nt][pr * 2 + 1];
                if (MODE == 1) {
                    float b0 = bias[e * FDIM + cg];
                    float b1v = bias[e * FDIM + cg + 1];
                    v0 = fmaxf(v0 + b0, 0.f) - fmaxf(b0, 0.f);
                    v1 = fmaxf(v1 + b1v, 0.f) - fmaxf(b1v, 0.f);
                    *(float2*)(g_h + (size_t)(off + mbase + r) * FDIM + cg) = make_float2(v0, v1);
                } else {
                    float s = s_sc[r];
                    *(float2*)(g_y + (size_t)s_ent[r] * HDIM + cg) = make_float2(s * v0, s * v1);
                }
            }
        }
    }
}

// ---------------- kernel 6: combine: out = x + stot*c_total + y[2t] + y[2t+1] ----------------
__global__ void __launch_bounds__(256) combine_kernel(const float* __restrict__ x, float* __restrict__ out) {
    const int t = blockIdx.x;
    const int tid = threadIdx.x;
    const float st = g_stot[t];
    const float4 xv = ((const float4*)(x + (size_t)t * HDIM))[tid];
    const float4 ct = ((const float4*)g_ctotal)[tid];
    const float4 y0 = ((const float4*)(g_y + (size_t)(2 * t) * HDIM))[tid];
    const float4 y1 = ((const float4*)(g_y + (size_t)(2 * t + 1) * HDIM))[tid];
    float4 o;
    o.x = xv.x + st * ct.x + y0.x + y1.x;
    o.y = xv.y + st * ct.y + y0.y + y1.y;
    o.z = xv.z + st * ct.z + y0.z + y1.z;
    o.w = xv.w + st * ct.w + y0.w + y1.w;
    ((float4*)(out + (size_t)t * HDIM))[tid] = o;
}

// ---------------- launch ----------------
extern "C" void kernel_launch(void* const* d_in, const int* in_sizes, int n_in,
                              void* d_out, int out_size) {
    (void)in_sizes; (void)n_in; (void)out_size;
    const float* x     = (const float*)d_in[0];
    const float* gamma = (const float*)d_in[1];
    const float* beta  = (const float*)d_in[2];
    const float* Wr    = (const float*)d_in[3];
    const float* br    = (const float*)d_in[4];
    const float* W1    = (const float*)d_in[5];
    const float* b1    = (const float*)d_in[6];
    const float* W2    = (const float*)d_in[7];
    const float* b2    = (const float*)d_in[8];
    float* out = (float*)d_out;

    const int smem = (2 * BM * AST + 2 * BK * BST) * (int)sizeof(float);  // 71680 B
    cudaFuncSetAttribute(gemm_kernel<1>, cudaFuncAttributeMaxDynamicSharedMemorySize, smem);
    cudaFuncSetAttribute(gemm_kernel<2>, cudaFuncAttributeMaxDynamicSharedMemorySize, smem);

    zero_kernel<<<1, 1024>>>();
    ctotal_kernel<<<dim3(HDIM / 256, 64), 256>>>(W2, b1, b2);
    ln_router_kernel<<<TOK, 256>>>(x, gamma, beta, Wr, br);
    offsets_kernel<<<1, 32>>>();
    gemm_kernel<1><<<dim3(FDIM / BN, TOK / BM, NEXP), 256, smem>>>(W1, b1);
    gemm_kernel<2><<<dim3(HDIM / BN, TOK / BM, NEXP), 256, smem>>>(W2, nullptr);
    combine_kernel<<<TOK, 256>>>(x, out);
}

// round 4
// speedup vs baseline: 1.0079x; 1.0079x over previous
#include <cuda_runtime.h>
#include <cstdint>

// Problem constants
#define TOK   16384        // B*S tokens
#define HDIM  1024
#define FDIM  4096
#define NEXP  8

// GEMM tiling
#define BM 128
#define BN 128
#define BK 32
#define AST 36             // A smem row stride (BK + 4): frag banks = laneid (conflict-free)
#define BST 136            // B smem row stride (BN + 8): frag banks = 8*tg + gid (conflict-free)

// ---------------- scratch (device globals; no runtime allocation) ----------------
__device__ float g_xn[(size_t)TOK * HDIM];          //  67 MB  normalized input (fp32, tf32-roundable)
__device__ float g_h[(size_t)TOK * 2 * FDIM];       // 537 MB  relu(xn@W1+b1)-relu(b1), compact per-expert rows
__device__ float g_y[(size_t)TOK * 2 * HDIM];       // 134 MB  s_k * (h @ W2), indexed by (t*2+k)
__device__ float g_ctotal[HDIM];
__device__ float g_score[TOK * 2];
__device__ float g_stot[TOK];
__device__ int   g_cnt[NEXP];
__device__ int   g_off[NEXP];
__device__ int   g_elist[NEXP * TOK];               // entries = t*2+k

// ---------------- helpers ----------------
__device__ __forceinline__ float to_tf32(float x) {
    unsigned u;
    asm("cvt.rna.tf32.f32 %0, %1;" : "=r"(u) : "f"(x));
    return __uint_as_float(u);
}

__device__ __forceinline__ void mma_tf32(float (&d)[4], const unsigned (&a)[4], const unsigned (&b)[2]) {
    asm volatile(
        "mma.sync.aligned.m16n8k8.row.col.f32.tf32.tf32.f32 "
        "{%0,%1,%2,%3}, {%4,%5,%6,%7}, {%8,%9}, {%0,%1,%2,%3};"
        : "+f"(d[0]), "+f"(d[1]), "+f"(d[2]), "+f"(d[3])
        : "r"(a[0]), "r"(a[1]), "r"(a[2]), "r"(a[3]), "r"(b[0]), "r"(b[1]));
}

// ---------------- kernel 0: zero counters + c_total accumulator ----------------
__global__ void zero_kernel() {
    int i = threadIdx.x;             // blockDim = 1024
    if (i < NEXP) g_cnt[i] = 0;
    g_ctotal[i] = 0.f;
}

// ---------------- kernel 1: c_total[h] = sum_e relu(b1_e)@W2_e + sum_e b2_e ----------------
__global__ void ctotal_kernel(const float* __restrict__ W2,
                              const float* __restrict__ b1,
                              const float* __restrict__ b2) {
    int h = blockIdx.x * 256 + threadIdx.x;          // grid.x = 4
    int chunk = blockIdx.y;                           // grid.y = 64, 512 (e,f) pairs each
    float acc = 0.f;
    for (int i = 0; i < 512; i++) {
        int ef = chunk * 512 + i;                     // ef = e*FDIM + f
        float bb = b1[ef];
        if (bb > 0.f) acc += bb * W2[(size_t)ef * HDIM + h];
    }
    if (acc != 0.f) atomicAdd(&g_ctotal[h], acc);
    if (chunk < NEXP) atomicAdd(&g_ctotal[h], b2[chunk * HDIM + h]);
}

// ---------------- kernel 2: LayerNorm + router (softmax over 8, top-2) ----------------
__global__ void __launch_bounds__(256) ln_router_kernel(const float* __restrict__ x,
                                                        const float* __restrict__ gamma,
                                                        const float* __restrict__ beta,
                                                        const float* __restrict__ Wr,
                                                        const float* __restrict__ br) {
    const int t = blockIdx.x;
    const int tid = threadIdx.x;
    const int lane = tid & 31, wid = tid >> 5;

    const float4 xv = ((const float4*)(x + (size_t)t * HDIM))[tid];
    float s1 = xv.x + xv.y + xv.z + xv.w;
    float s2 = xv.x*xv.x + xv.y*xv.y + xv.z*xv.z + xv.w*xv.w;
    #pragma unroll
    for (int o = 16; o; o >>= 1) {
        s1 += __shfl_xor_sync(0xffffffffu, s1, o);
        s2 += __shfl_xor_sync(0xffffffffu, s2, o);
    }
    __shared__ float rs1[8], rs2[8];
    __shared__ float s_mu, s_rs;
    if (lane == 0) { rs1[wid] = s1; rs2[wid] = s2; }
    __syncthreads();
    if (wid == 0) {
        float a = (lane < 8) ? rs1[lane] : 0.f;
        float b = (lane < 8) ? rs2[lane] : 0.f;
        #pragma unroll
        for (int o = 4; o; o >>= 1) {
            a += __shfl_xor_sync(0xffffffffu, a, o);
            b += __shfl_xor_sync(0xffffffffu, b, o);
        }
        if (lane == 0) {
            float mu = a * (1.f / HDIM);
            float var = b * (1.f / HDIM) - mu * mu;
            s_mu = mu;
            s_rs = rsqrtf(var + 1e-5f);
        }
    }
    __syncthreads();
    const float mu = s_mu, rs = s_rs;

    const float4 g  = ((const float4*)gamma)[tid];
    const float4 be = ((const float4*)beta)[tid];
    float4 xn;
    xn.x = (xv.x - mu) * rs * g.x + be.x;
    xn.y = (xv.y - mu) * rs * g.y + be.y;
    xn.z = (xv.z - mu) * rs * g.z + be.z;
    xn.w = (xv.w - mu) * rs * g.w + be.w;
    ((float4*)(g_xn + (size_t)t * HDIM))[tid] = xn;

    // router logits: xn @ Wr   (Wr is [H, E] row-major)
    float lg[NEXP];
    #pragma unroll
    for (int e = 0; e < NEXP; e++) lg[e] = 0.f;
    const int h0 = tid * 4;
    const float xns[4] = {xn.x, xn.y, xn.z, xn.w};
    #pragma unroll
    for (int j = 0; j < 4; j++) {
        const float4 w0 = ((const float4*)(Wr + (size_t)(h0 + j) * NEXP))[0];
        const float4 w1 = ((const float4*)(Wr + (size_t)(h0 + j) * NEXP))[1];
        lg[0] += xns[j] * w0.x; lg[1] += xns[j] * w0.y;
        lg[2] += xns[j] * w0.z; lg[3] += xns[j] * w0.w;
        lg[4] += xns[j] * w1.x; lg[5] += xns[j] * w1.y;
        lg[6] += xns[j] * w1.z; lg[7] += xns[j] * w1.w;
    }
    #pragma unroll
    for (int e = 0; e < NEXP; e++)
        #pragma unroll
        for (int o = 16; o; o >>= 1)
            lg[e] += __shfl_xor_sync(0xffffffffu, lg[e], o);

    __shared__ float lred[8][NEXP];
    if (lane == 0)
        #pragma unroll
        for (int e = 0; e < NEXP; e++) lred[wid][e] = lg[e];
    __syncthreads();

    if (tid == 0) {
        float L[NEXP];
        #pragma unroll
        for (int e = 0; e < NEXP; e++) {
            L[e] = br[e];
            #pragma unroll
            for (int w = 0; w < 8; w++) L[e] += lred[w][e];
        }
        float mx = L[0];
        #pragma unroll
        for (int e = 1; e < NEXP; e++) mx = fmaxf(mx, L[e]);
        float ex[NEXP], den = 0.f;
        #pragma unroll
        for (int e = 0; e < NEXP; e++) { ex[e] = __expf(L[e] - mx); den += ex[e]; }
        int i0 = 0;
        #pragma unroll
        for (int e = 1; e < NEXP; e++) if (L[e] > L[i0]) i0 = e;
        int i1 = (i0 == 0) ? 1 : 0;
        #pragma unroll
        for (int e = 0; e < NEXP; e++) if (e != i0 && L[e] > L[i1]) i1 = e;
        float inv = 1.f / den;
        float sc0 = ex[i0] * inv, sc1 = ex[i1] * inv;
        g_score[2 * t]     = sc0;
        g_score[2 * t + 1] = sc1;
        g_stot[t] = sc0 + sc1;
        int p0 = atomicAdd(&g_cnt[i0], 1);
        g_elist[i0 * TOK + p0] = 2 * t;
        int p1 = atomicAdd(&g_cnt[i1], 1);
        g_elist[i1 * TOK + p1] = 2 * t + 1;
    }
}

// ---------------- kernel 3: exclusive scan of counts (E=8) ----------------
__global__ void offsets_kernel() {
    if (threadIdx.x == 0) {
        int s = 0;
        #pragma unroll
        for (int e = 0; e < NEXP; e++) { g_off[e] = s; s += g_cnt[e]; }
    }
}

// ---------------- GEMM (tf32 mma.sync), MODE 1: h = relu(xn@W1+b1)-relu(b1); MODE 2: y = s*(h@W2) ----------------
template <int MODE>
__global__ void __launch_bounds__(256, 1) gemm_kernel(const float* __restrict__ Bglob,
                                                      const float* __restrict__ bias) {
    constexpr int KDIM = (MODE == 1) ? HDIM : FDIM;
    constexpr int LDB  = (MODE == 1) ? FDIM : HDIM;
    constexpr int NDIM = (MODE == 1) ? FDIM : HDIM;
    constexpr int NKT  = KDIM / BK;

    const int e = blockIdx.z;
    const int cnt = g_cnt[e];
    const int mbase = blockIdx.y * BM;
    if (mbase >= cnt) return;
    const int nb = blockIdx.x * BN;
    const int off = g_off[e];

    extern __shared__ float sm[];
    float* As = sm;                          // 2 * BM * AST
    float* Bs = sm + 2 * BM * AST;           // 2 * BK * BST
    __shared__ int   s_rowoff[BM];
    __shared__ int   s_ent[BM];
    __shared__ float s_sc[BM];

    const int tid = threadIdx.x;
    if (tid < BM) {
        int r = mbase + tid;
        int rc = (r < cnt) ? r : (cnt - 1);
        int ent = g_elist[e * TOK + rc];
        if (MODE == 1) {
            s_rowoff[tid] = (ent >> 1) * HDIM;
        } else {
            s_rowoff[tid] = (off + rc) * FDIM;
            s_ent[tid] = ent;
            s_sc[tid]  = g_score[ent];
        }
    }
    __syncthreads();

    const float* Ag = (MODE == 1) ? g_xn : g_h;
    const float* Bptr = Bglob + (size_t)e * KDIM * NDIM + nb;

    const int arow = tid >> 3;               // 0..31 (+32/pass)
    const int acol = (tid & 7) * 4;
    const int bcol = (tid & 31) * 4;
    const int brow = tid >> 5;               // 0..7 (+8/pass)

    const int warp = tid >> 5, lane = tid & 31;
    const int wm = warp >> 2, wn = warp & 3; // warp tile 64 x 32
    const int gid = lane >> 2, tg = lane & 3;

    float acc[4][4][4];
    #pragma unroll
    for (int i = 0; i < 4; i++)
        #pragma unroll
        for (int j = 0; j < 4; j++)
            #pragma unroll
            for (int c = 0; c < 4; c++) acc[i][j][c] = 0.f;

    float4 ra[4], rb[4];

    auto load_g = [&](int k0) {
        #pragma unroll
        for (int p = 0; p < 4; p++) {
            int r = arow + p * 32;
            ra[p] = *(const float4*)(Ag + (size_t)s_rowoff[r] + k0 + acol);
            int kk = brow + p * 8;
            rb[p] = *(const float4*)(Bptr + (size_t)(k0 + kk) * LDB + bcol);
        }
    };
    auto store_s = [&](int buf) {
        float* A  = As + buf * BM * AST;
        float* Bb = Bs + buf * BK * BST;
        #pragma unroll
        for (int p = 0; p < 4; p++) {
            int r = arow + p * 32;
            float4 av = make_float4(to_tf32(ra[p].x), to_tf32(ra[p].y), to_tf32(ra[p].z), to_tf32(ra[p].w));
            *(float4*)(A + r * AST + acol) = av;
            int kk = brow + p * 8;
            float4 bv = make_float4(to_tf32(rb[p].x), to_tf32(rb[p].y), to_tf32(rb[p].z), to_tf32(rb[p].w));
            *(float4*)(Bb + kk * BST + bcol) = bv;
        }
    };
    auto compute = [&](int buf) {
        const float* A  = As + buf * BM * AST;
        const float* Bb = Bs + buf * BK * BST;
        #pragma unroll
        for (int ks = 0; ks < 4; ks++) {
            const int kb = ks * 8;
            unsigned af[4][4];
            #pragma unroll
            for (int mt = 0; mt < 4; mt++) {
                const float* ap = A + (wm * 64 + mt * 16 + gid) * AST + kb + tg;
                af[mt][0] = __float_as_uint(ap[0]);
                af[mt][2] = __float_as_uint(ap[4]);
                af[mt][1] = __float_as_uint(ap[8 * AST]);
                af[mt][3] = __float_as_uint(ap[8 * AST + 4]);
            }
            unsigned bf[4][2];
            #pragma unroll
            for (int nt = 0; nt < 4; nt++) {
                const int c = wn * 32 + nt * 8 + gid;
                bf[nt][0] = __float_as_uint(Bb[(kb + tg) * BST + c]);
                bf[nt][1] = __float_as_uint(Bb[(kb + tg + 4) * BST + c]);
            }
            #pragma unroll
            for (int mt = 0; mt < 4; mt++)
                #pragma unroll
                for (int nt = 0; nt < 4; nt++)
                    mma_tf32(acc[mt][nt], af[mt], bf[nt]);
        }
    };

    load_g(0);
    store_s(0);
    __syncthreads();
    for (int kt = 0; kt < NKT; kt++) {
        if (kt + 1 < NKT) load_g((kt + 1) * BK);
        compute(kt & 1);
        if (kt + 1 < NKT) store_s((kt + 1) & 1);
        __syncthreads();
    }

    // epilogue
    #pragma unroll
    for (int mt = 0; mt < 4; mt++) {
        #pragma unroll
        for (int pr = 0; pr < 2; pr++) {
            const int r = wm * 64 + mt * 16 + gid + pr * 8;
            if (mbase + r >= cnt) continue;
            #pragma unroll
            for (int nt = 0; nt < 4; nt++) {
                const int c  = wn * 32 + nt * 8 + 2 * tg;
                const int cg = nb + c;
                float v0 = acc[mt][nt][pr * 2 + 0];
                float v1 = acc[mt][nt][pr * 2 + 1];
                if (MODE == 1) {
                    float b0 = bias[e * FDIM + cg];
                    float b1v = bias[e * FDIM + cg + 1];
                    v0 = fmaxf(v0 + b0, 0.f) - fmaxf(b0, 0.f);
                    v1 = fmaxf(v1 + b1v, 0.f) - fmaxf(b1v, 0.f);
                    *(float2*)(g_h + (size_t)(off + mbase + r) * FDIM + cg) = make_float2(v0, v1);
                } else {
                    float s = s_sc[r];
                    *(float2*)(g_y + (size_t)s_ent[r] * HDIM + cg) = make_float2(s * v0, s * v1);
                }
            }
        }
    }
}

// ---------------- kernel 6: combine: out = x + stot*c_total + y[2t] + y[2t+1] ----------------
__global__ void __launch_bounds__(256) combine_kernel(const float* __restrict__ x, float* __restrict__ out) {
    const int t = blockIdx.x;
    const int tid = threadIdx.x;
    const float st = g_stot[t];
    const float4 xv = ((const float4*)(x + (size_t)t * HDIM))[tid];
    const float4 ct = ((const float4*)g_ctotal)[tid];
    const float4 y0 = ((const float4*)(g_y + (size_t)(2 * t) * HDIM))[tid];
    const float4 y1 = ((const float4*)(g_y + (size_t)(2 * t + 1) * HDIM))[tid];
    float4 o;
    o.x = xv.x + st * ct.x + y0.x + y1.x;
    o.y = xv.y + st * ct.y + y0.y + y1.y;
    o.z = xv.z + st * ct.z + y0.z + y1.z;
    o.w = xv.w + st * ct.w + y0.w + y1.w;
    ((float4*)(out + (size_t)t * HDIM))[tid] = o;
}

// ---------------- launch ----------------
extern "C" void kernel_launch(void* const* d_in, const int* in_sizes, int n_in,
                              void* d_out, int out_size) {
    (void)in_sizes; (void)n_in; (void)out_size;
    const float* x     = (const float*)d_in[0];
    const float* gamma = (const float*)d_in[1];
    const float* beta  = (const float*)d_in[2];
    const float* Wr    = (const float*)d_in[3];
    const float* br    = (const float*)d_in[4];
    const float* W1    = (const float*)d_in[5];
    const float* b1    = (const float*)d_in[6];
    const float* W2    = (const float*)d_in[7];
    const float* b2    = (const float*)d_in[8];
    float* out = (float*)d_out;

    const int smem = (2 * BM * AST + 2 * BK * BST) * (int)sizeof(float);  // 71680 B
    cudaFuncSetAttribute(gemm_kernel<1>, cudaFuncAttributeMaxDynamicSharedMemorySize, smem);
    cudaFuncSetAttribute(gemm_kernel<2>, cudaFuncAttributeMaxDynamicSharedMemorySize, smem);

    zero_kernel<<<1, 1024>>>();
    ctotal_kernel<<<dim3(HDIM / 256, 64), 256>>>(W2, b1, b2);
    ln_router_kernel<<<TOK, 256>>>(x, gamma, beta, Wr, br);
    offsets_kernel<<<1, 32>>>();
    gemm_kernel<1><<<dim3(FDIM / BN, TOK / BM, NEXP), 256, smem>>>(W1, b1);
    gemm_kernel<2><<<dim3(HDIM / BN, TOK / BM, NEXP), 256, smem>>>(W2, nullptr);
    combine_kernel<<<TOK, 256>>>(x, out);
}

// round 6
// speedup vs baseline: 1.6493x; 1.6363x over previous
#include <cuda_runtime.h>
#include <cuda_bf16.h>
#include <cstdint>

#define TOK   16384
#define HDIM  1024
#define FDIM  4096
#define NEXP  8

#define BM 128
#define BN 256
#define BK 32
#define NS 4
#define A_BYTES     8192           // 128 rows x 64 B (32 bf16)
#define B_BYTES     16384          // 256 rows x 64 B
#define STAGE_BYTES 24576

// ---------------- scratch (device globals; no runtime allocation) ----------------
__device__ __nv_bfloat16 g_xn [(size_t)TOK * HDIM];          //  34 MB
__device__ __nv_bfloat16 g_h  [(size_t)TOK * 2 * FDIM];      // 268 MB
__device__ float         g_y  [(size_t)TOK * 2 * HDIM];      // 134 MB
__device__ __nv_bfloat16 g_w1t[(size_t)NEXP * FDIM * HDIM];  //  67 MB  W1^T [e][f][h] K-major
__device__ __nv_bfloat16 g_w2t[(size_t)NEXP * HDIM * FDIM];  //  67 MB  W2^T [e][h][f] K-major
__device__ float g_ctotal[HDIM];
__device__ float g_score[TOK * 2];
__device__ float g_stot[TOK];
__device__ int   g_cnt[NEXP];
__device__ int   g_off[NEXP];
__device__ int   g_elist[NEXP * TOK];

// ---------------- helpers ----------------
__device__ __forceinline__ uint32_t smem_u32(const void* p) {
    uint32_t a;
    asm("{ .reg .u64 t; cvta.to.shared.u64 t, %1; cvt.u32.u64 %0, t; }" : "=r"(a) : "l"(p));
    return a;
}
__device__ __forceinline__ void cp16(uint32_t dst, const void* src) {
    asm volatile("cp.async.cg.shared.global [%0], [%1], 16;" :: "r"(dst), "l"(src));
}
__device__ __forceinline__ void cp_commit() { asm volatile("cp.async.commit_group;"); }
template <int N> __device__ __forceinline__ void cp_wait() {
    asm volatile("cp.async.wait_group %0;" :: "n"(N));
}
__device__ __forceinline__ void ldsm4(uint32_t (&r)[4], uint32_t addr) {
    asm volatile("ldmatrix.sync.aligned.m8n8.x4.shared.b16 {%0,%1,%2,%3}, [%4];"
                 : "=r"(r[0]), "=r"(r[1]), "=r"(r[2]), "=r"(r[3]) : "r"(addr));
}
__device__ __forceinline__ void mma_bf16(float (&d)[4], const uint32_t (&a)[4],
                                         uint32_t b0, uint32_t b1) {
    asm volatile(
        "mma.sync.aligned.m16n8k16.row.col.f32.bf16.bf16.f32 "
        "{%0,%1,%2,%3}, {%4,%5,%6,%7}, {%8,%9}, {%0,%1,%2,%3};"
        : "+f"(d[0]), "+f"(d[1]), "+f"(d[2]), "+f"(d[3])
        : "r"(a[0]), "r"(a[1]), "r"(a[2]), "r"(a[3]), "r"(b0), "r"(b1));
}

// ---------------- kernel 0 ----------------
__global__ void zero_kernel() {
    int i = threadIdx.x;
    if (i < NEXP) g_cnt[i] = 0;
    g_ctotal[i] = 0.f;
}

// ---------------- c_total (exact fp32) ----------------
__global__ void ctotal_kernel(const float* __restrict__ W2, const float* __restrict__ b1,
                              const float* __restrict__ b2) {
    int h = blockIdx.x * 256 + threadIdx.x;
    int chunk = blockIdx.y;
    float acc = 0.f;
    for (int i = 0; i < 512; i++) {
        int ef = chunk * 512 + i;
        float bb = b1[ef];
        if (bb > 0.f) acc += bb * W2[(size_t)ef * HDIM + h];
    }
    if (acc != 0.f) atomicAdd(&g_ctotal[h], acc);
    if (chunk < NEXP) atomicAdd(&g_ctotal[h], b2[chunk * HDIM + h]);
}

// ---------------- transpose weights -> K-major [E][N][K], bf16 ----------------
__global__ void transpose_w(const float* __restrict__ src, int which) {
    __shared__ float t[32][33];
    const int R = which ? FDIM : HDIM;      // src rows  (K)
    const int C = which ? HDIM : FDIM;      // src cols  (N, contiguous)
    __nv_bfloat16* dst = which ? g_w2t : g_w1t;
    const size_t base = (size_t)blockIdx.z * R * C;
    const int c0 = blockIdx.x * 32, r0 = blockIdx.y * 32;
    const int tx = threadIdx.x, ty = threadIdx.y;
    #pragma unroll
    for (int j = ty; j < 32; j += 8)
        t[j][tx] = src[base + (size_t)(r0 + j) * C + c0 + tx];
    __syncthreads();
    #pragma unroll
    for (int j = ty; j < 32; j += 8)
        dst[base + (size_t)(c0 + j) * R + r0 + tx] = __float2bfloat16_rn(t[tx][j]);
}

// ---------------- LayerNorm + router ----------------
__global__ void __launch_bounds__(256) ln_router_kernel(const float* __restrict__ x,
                                                        const float* __restrict__ gamma,
                                                        const float* __restrict__ beta,
                                                        const float* __restrict__ Wr,
                                                        const float* __restrict__ br) {
    const int t = blockIdx.x;
    const int tid = threadIdx.x;
    const int lane = tid & 31, wid = tid >> 5;

    const float4 xv = ((const float4*)(x + (size_t)t * HDIM))[tid];
    float s1 = xv.x + xv.y + xv.z + xv.w;
    float s2 = xv.x*xv.x + xv.y*xv.y + xv.z*xv.z + xv.w*xv.w;
    #pragma unroll
    for (int o = 16; o; o >>= 1) {
        s1 += __shfl_xor_sync(0xffffffffu, s1, o);
        s2 += __shfl_xor_sync(0xffffffffu, s2, o);
    }
    __shared__ float rs1[8], rs2[8], s_mu, s_rs;
    if (lane == 0) { rs1[wid] = s1; rs2[wid] = s2; }
    __syncthreads();
    if (wid == 0) {
        float a = (lane < 8) ? rs1[lane] : 0.f;
        float b = (lane < 8) ? rs2[lane] : 0.f;
        #pragma unroll
        for (int o = 4; o; o >>= 1) {
            a += __shfl_xor_sync(0xffffffffu, a, o);
            b += __shfl_xor_sync(0xffffffffu, b, o);
        }
        if (lane == 0) {
            float mu = a * (1.f / HDIM);
            float var = b * (1.f / HDIM) - mu * mu;
            s_mu = mu; s_rs = rsqrtf(var + 1e-5f);
        }
    }
    __syncthreads();
    const float mu = s_mu, rs = s_rs;

    const float4 g  = ((const float4*)gamma)[tid];
    const float4 be = ((const float4*)beta)[tid];
    float4 xn;
    xn.x = (xv.x - mu) * rs * g.x + be.x;
    xn.y = (xv.y - mu) * rs * g.y + be.y;
    xn.z = (xv.z - mu) * rs * g.z + be.z;
    xn.w = (xv.w - mu) * rs * g.w + be.w;

    float lg[NEXP];
    #pragma unroll
    for (int e = 0; e < NEXP; e++) lg[e] = 0.f;
    const int h0 = tid * 4;
    const float xns[4] = {xn.x, xn.y, xn.z, xn.w};
    #pragma unroll
    for (int j = 0; j < 4; j++) {
        const float4 w0 = ((const float4*)(Wr + (size_t)(h0 + j) * NEXP))[0];
        const float4 w1 = ((const float4*)(Wr + (size_t)(h0 + j) * NEXP))[1];
        lg[0] += xns[j]*w0.x; lg[1] += xns[j]*w0.y; lg[2] += xns[j]*w0.z; lg[3] += xns[j]*w0.w;
        lg[4] += xns[j]*w1.x; lg[5] += xns[j]*w1.y; lg[6] += xns[j]*w1.z; lg[7] += xns[j]*w1.w;
    }
    #pragma unroll
    for (int e = 0; e < NEXP; e++)
        #pragma unroll
        for (int o = 16; o; o >>= 1)
            lg[e] += __shfl_xor_sync(0xffffffffu, lg[e], o);

    __shared__ float lred[8][NEXP];
    if (lane == 0)
        #pragma unroll
        for (int e = 0; e < NEXP; e++) lred[wid][e] = lg[e];
    __syncthreads();

    if (tid == 0) {
        float L[NEXP];
        #pragma unroll
        for (int e = 0; e < NEXP; e++) {
            L[e] = br[e];
            #pragma unroll
            for (int w = 0; w < 8; w++) L[e] += lred[w][e];
        }
        float mx = L[0];
        #pragma unroll
        for (int e = 1; e < NEXP; e++) mx = fmaxf(mx, L[e]);
        float ex[NEXP], den = 0.f;
        #pragma unroll
        for (int e = 0; e < NEXP; e++) { ex[e] = __expf(L[e] - mx); den += ex[e]; }
        int i0 = 0;
        #pragma unroll
        for (int e = 1; e < NEXP; e++) if (L[e] > L[i0]) i0 = e;
        int i1 = (i0 == 0) ? 1 : 0;
        #pragma unroll
        for (int e = 0; e < NEXP; e++) if (e != i0 && L[e] > L[i1]) i1 = e;
        float inv = 1.f / den;
        float sc0 = ex[i0] * inv, sc1 = ex[i1] * inv;
        g_score[2*t] = sc0; g_score[2*t+1] = sc1;
        g_stot[t] = sc0 + sc1;
        int p0 = atomicAdd(&g_cnt[i0], 1); g_elist[i0 * TOK + p0] = 2*t;
        int p1 = atomicAdd(&g_cnt[i1], 1); g_elist[i1 * TOK + p1] = 2*t + 1;
    }

    __nv_bfloat162 h01 = __floats2bfloat162_rn(xn.x, xn.y);
    __nv_bfloat162 h23 = __floats2bfloat162_rn(xn.z, xn.w);
    uint2 pk = make_uint2(*(uint32_t*)&h01, *(uint32_t*)&h23);
    *(uint2*)(g_xn + (size_t)t * HDIM + tid * 4) = pk;
}

__global__ void offsets_kernel() {
    if (threadIdx.x == 0) {
        int s = 0;
        #pragma unroll
        for (int e = 0; e < NEXP; e++) { g_off[e] = s; s += g_cnt[e]; }
    }
}

// ---------------- bf16 mma.sync GEMM (ldmatrix + cp.async, 4 stages) ----------------
// MODE 1: g_h[off+row] = bf16( relu(xn@W1+b1) - relu(b1) )   K=1024, N=4096
// MODE 2: g_y[ent]     = score * (g_h @ W2)                  K=4096, N=1024
template <int MODE>
__global__ void __launch_bounds__(256, 1) mm_gemm(const float* __restrict__ bias) {
    constexpr int KD  = (MODE == 1) ? HDIM : FDIM;
    constexpr int ND  = (MODE == 1) ? FDIM : HDIM;
    constexpr int NKT = KD / BK;

    const int e = blockIdx.z;
    const int cnt = g_cnt[e];
    const int mb0 = blockIdx.y * BM;
    if (mb0 >= cnt) return;
    const int nb = blockIdx.x * BN;
    const int off = g_off[e];

    extern __shared__ char dyn[];
    __shared__ int   s_rowoff[BM];
    __shared__ int   s_ent[BM];
    __shared__ float s_sc[BM];

    const int tid = threadIdx.x;
    const int lane = tid & 31, wid = tid >> 5;
    const uint32_t sbase = smem_u32(dyn);

    if (tid < BM) {
        int r = mb0 + tid;
        int rc = (r < cnt) ? r : (cnt - 1);
        int ent = g_elist[e * TOK + rc];
        if (MODE == 1) {
            s_rowoff[tid] = (ent >> 1) * HDIM;
        } else {
            s_rowoff[tid] = (off + rc) * FDIM;
            s_ent[tid] = ent;
            s_sc[tid]  = g_score[ent];
        }
    }
    __syncthreads();

    const __nv_bfloat16* Ag = (MODE == 1) ? g_xn : g_h;
    const __nv_bfloat16* Bg = ((MODE == 1) ? g_w1t : g_w2t) + (size_t)(e * ND + nb) * KD;

    // cp.async mapping: A: thread -> row tid/2, chunks {2*(tid&1), 2*(tid&1)+1}
    //                   B: thread -> row tid, chunks 0..3
    const int arow = tid >> 1;
    const int ac0  = (tid & 1) * 2;

    auto load_stage = [&](int kt) {
        const uint32_t sa = sbase + (kt % NS) * STAGE_BYTES;
        const int k0 = kt * BK;
        const __nv_bfloat16* asrc = Ag + (size_t)s_rowoff[arow] + k0;
        const uint32_t asw = (arow >> 1) & 3;
        cp16(sa + arow * 64 + (((ac0    ) ^ asw) << 4), asrc + ac0 * 8);
        cp16(sa + arow * 64 + (((ac0 + 1) ^ asw) << 4), asrc + ac0 * 8 + 8);
        const __nv_bfloat16* bsrc = Bg + (size_t)tid * KD + k0;
        const uint32_t sb = sa + A_BYTES + tid * 64;
        const uint32_t bsw = (tid >> 1) & 3;
        #pragma unroll
        for (int c = 0; c < 4; c++)
            cp16(sb + ((c ^ bsw) << 4), bsrc + c * 8);
    };

    // warp layout: 2 (m) x 4 (n); warp tile 64x64
    const int wm = wid & 1, wn = wid >> 1;
    const int jj = lane >> 3, ii = lane & 7;
    const int rA  = (jj & 1) * 8 + ii;      // ldsm row within 16 (A)
    const int chA = jj >> 1;
    const int sxA = (rA >> 1) & 3;
    const int rB  = (jj >> 1) * 8 + ii;     // ldsm row within 16 (B)
    const int chB = jj & 1;
    const int sxB = (rB >> 1) & 3;

    float acc[4][8][4];
    #pragma unroll
    for (int i = 0; i < 4; i++)
        #pragma unroll
        for (int j = 0; j < 8; j++)
            #pragma unroll
            for (int c = 0; c < 4; c++) acc[i][j][c] = 0.f;

    load_stage(0); cp_commit();
    load_stage(1); cp_commit();
    load_stage(2); cp_commit();

    #pragma unroll 1
    for (int kt = 0; kt < NKT; kt++) {
        cp_wait<NS - 2>();
        __syncthreads();
        const int nl = kt + NS - 1;
        if (nl < NKT) load_stage(nl);
        cp_commit();

        const uint32_t sa = sbase + (kt % NS) * STAGE_BYTES;
        const uint32_t aw = sa + (wm * 64 + rA) * 64;
        const uint32_t bw = sa + A_BYTES + (wn * 64 + rB) * 64;
        #pragma unroll
        for (int ks = 0; ks < 2; ks++) {
            uint32_t af[4][4];
            #pragma unroll
            for (int mb = 0; mb < 4; mb++)
                ldsm4(af[mb], aw + mb * 1024 + (((2*ks + chA) ^ sxA) << 4));
            uint32_t bf[4][4];
            #pragma unroll
            for (int np = 0; np < 4; np++)
                ldsm4(bf[np], bw + np * 1024 + (((2*ks + chB) ^ sxB) << 4));
            #pragma unroll
            for (int mb = 0; mb < 4; mb++)
                #pragma unroll
                for (int np = 0; np < 4; np++) {
                    mma_bf16(acc[mb][np*2+0], af[mb], bf[np][0], bf[np][1]);
                    mma_bf16(acc[mb][np*2+1], af[mb], bf[np][2], bf[np][3]);
                }
        }
    }

    // ---------------- epilogue ----------------
    const int qr = lane >> 2;             // 0..7
    const int qc = (lane & 3) * 2;
    #pragma unroll
    for (int mb = 0; mb < 4; mb++) {
        #pragma unroll
        for (int half = 0; half < 2; half++) {
            const int rloc = wm * 64 + mb * 16 + qr + half * 8;
            if (mb0 + rloc >= cnt) continue;
            #pragma unroll
            for (int nblk = 0; nblk < 8; nblk++) {
                const int cg = nb + wn * 64 + nblk * 8 + qc;
                float v0 = acc[mb][nblk][half * 2 + 0];
                float v1 = acc[mb][nblk][half * 2 + 1];
                if (MODE == 1) {
                    const float2 bb = *(const float2*)(bias + e * FDIM + cg);
                    v0 = fmaxf(v0 + bb.x, 0.f) - fmaxf(bb.x, 0.f);
                    v1 = fmaxf(v1 + bb.y, 0.f) - fmaxf(bb.y, 0.f);
                    __nv_bfloat162 pk = __floats2bfloat162_rn(v0, v1);
                    *(uint32_t*)(g_h + (size_t)(off + mb0 + rloc) * FDIM + cg) = *(uint32_t*)&pk;
                } else {
                    const float s = s_sc[rloc];
                    *(float2*)(g_y + (size_t)s_ent[rloc] * HDIM + cg) = make_float2(s * v0, s * v1);
                }
            }
        }
    }
}

// ---------------- combine ----------------
__global__ void __launch_bounds__(256) combine_kernel(const float* __restrict__ x,
                                                      float* __restrict__ out) {
    const int t = blockIdx.x;
    const int tid = threadIdx.x;
    const float st = g_stot[t];
    const float4 xv = ((const float4*)(x + (size_t)t * HDIM))[tid];
    const float4 ct = ((const float4*)g_ctotal)[tid];
    const float4 y0 = ((const float4*)(g_y + (size_t)(2*t)     * HDIM))[tid];
    const float4 y1 = ((const float4*)(g_y + (size_t)(2*t + 1) * HDIM))[tid];
    float4 o;
    o.x = xv.x + st * ct.x + y0.x + y1.x;
    o.y = xv.y + st * ct.y + y0.y + y1.y;
    o.z = xv.z + st * ct.z + y0.z + y1.z;
    o.w = xv.w + st * ct.w + y0.w + y1.w;
    ((float4*)(out + (size_t)t * HDIM))[tid] = o;
}

// ---------------- launch ----------------
extern "C" void kernel_launch(void* const* d_in, const int* in_sizes, int n_in,
                              void* d_out, int out_size) {
    (void)in_sizes; (void)n_in; (void)out_size;
    const float* x     = (const float*)d_in[0];
    const float* gamma = (const float*)d_in[1];
    const float* beta  = (const float*)d_in[2];
    const float* Wr    = (const float*)d_in[3];
    const float* br    = (const float*)d_in[4];
    const float* W1    = (const float*)d_in[5];
    const float* b1    = (const float*)d_in[6];
    const float* W2    = (const float*)d_in[7];
    const float* b2    = (const float*)d_in[8];
    float* out = (float*)d_out;

    const int smem = NS * STAGE_BYTES;   // 98304 B
    cudaFuncSetAttribute(mm_gemm<1>, cudaFuncAttributeMaxDynamicSharedMemorySize, smem);
    cudaFuncSetAttribute(mm_gemm<2>, cudaFuncAttributeMaxDynamicSharedMemorySize, smem);

    zero_kernel<<<1, 1024>>>();
    ctotal_kernel<<<dim3(HDIM / 256, 64), 256>>>(W2, b1, b2);
    transpose_w<<<dim3(FDIM / 32, HDIM / 32, NEXP), dim3(32, 8)>>>(W1, 0);
    transpose_w<<<dim3(HDIM / 32, FDIM / 32, NEXP), dim3(32, 8)>>>(W2, 1);
    ln_router_kernel<<<TOK, 256>>>(x, gamma, beta, Wr, br);
    offsets_kernel<<<1, 32>>>();
    mm_gemm<1><<<dim3(FDIM / BN, (2 * TOK) / BM, NEXP), 256, smem>>>(b1);
    mm_gemm<2><<<dim3(HDIM / BN, (2 * TOK) / BM, NEXP), 256, smem>>>(nullptr);
    combine_kernel<<<TOK, 256>>>(x, out);
}

// round 7
// speedup vs baseline: 2.0849x; 1.2641x over previous
#include <cuda_runtime.h>
#include <cuda_bf16.h>
#include <cstdint>

#define TOK   16384
#define HDIM  1024
#define FDIM  4096
#define NEXP  8

#define BM 128
#define BN 256
#define BK 32
#define NS 4
#define A_BYTES     8192           // 128 rows x 64 B (32 bf16)
#define B_BYTES     16384          // 256 rows x 64 B
#define STAGE_BYTES 24576
#define NTHR 512

// ---------------- scratch (device globals; no runtime allocation) ----------------
__device__ __nv_bfloat16 g_xn [(size_t)TOK * HDIM];          //  34 MB
__device__ __nv_bfloat16 g_h  [(size_t)TOK * 2 * FDIM];      // 268 MB
__device__ float         g_y  [(size_t)TOK * 2 * HDIM];      // 134 MB
__device__ __nv_bfloat16 g_w1t[(size_t)NEXP * FDIM * HDIM];  //  67 MB  W1^T [e][f][h] K-major
__device__ __nv_bfloat16 g_w2t[(size_t)NEXP * HDIM * FDIM];  //  67 MB  W2^T [e][h][f] K-major
__device__ float g_ctotal[HDIM];
__device__ float g_score[TOK * 2];
__device__ float g_stot[TOK];
__device__ int   g_cnt[NEXP];
__device__ int   g_off[NEXP];
__device__ int   g_elist[NEXP * TOK];

// ---------------- helpers ----------------
__device__ __forceinline__ uint32_t smem_u32(const void* p) {
    uint32_t a;
    asm("{ .reg .u64 t; cvta.to.shared.u64 t, %1; cvt.u32.u64 %0, t; }" : "=r"(a) : "l"(p));
    return a;
}
__device__ __forceinline__ void cp16(uint32_t dst, const void* src) {
    asm volatile("cp.async.cg.shared.global [%0], [%1], 16;" :: "r"(dst), "l"(src));
}
__device__ __forceinline__ void cp_commit() { asm volatile("cp.async.commit_group;"); }
template <int N> __device__ __forceinline__ void cp_wait() {
    asm volatile("cp.async.wait_group %0;" :: "n"(N));
}
__device__ __forceinline__ void ldsm4(uint32_t (&r)[4], uint32_t addr) {
    asm volatile("ldmatrix.sync.aligned.m8n8.x4.shared.b16 {%0,%1,%2,%3}, [%4];"
                 : "=r"(r[0]), "=r"(r[1]), "=r"(r[2]), "=r"(r[3]) : "r"(addr));
}
__device__ __forceinline__ void mma_bf16(float (&d)[4], const uint32_t (&a)[4],
                                         uint32_t b0, uint32_t b1) {
    asm volatile(
        "mma.sync.aligned.m16n8k16.row.col.f32.bf16.bf16.f32 "
        "{%0,%1,%2,%3}, {%4,%5,%6,%7}, {%8,%9}, {%0,%1,%2,%3};"
        : "+f"(d[0]), "+f"(d[1]), "+f"(d[2]), "+f"(d[3])
        : "r"(a[0]), "r"(a[1]), "r"(a[2]), "r"(a[3]), "r"(b0), "r"(b1));
}

// ---------------- kernel 0 ----------------
__global__ void zero_kernel() {
    int i = threadIdx.x;
    if (i < NEXP) g_cnt[i] = 0;
    g_ctotal[i] = 0.f;
}

// ---------------- c_total (exact fp32) ----------------
__global__ void ctotal_kernel(const float* __restrict__ W2, const float* __restrict__ b1,
                              const float* __restrict__ b2) {
    int h = blockIdx.x * 256 + threadIdx.x;
    int chunk = blockIdx.y;
    float acc = 0.f;
    for (int i = 0; i < 512; i++) {
        int ef = chunk * 512 + i;
        float bb = b1[ef];
        if (bb > 0.f) acc += bb * W2[(size_t)ef * HDIM + h];
    }
    if (acc != 0.f) atomicAdd(&g_ctotal[h], acc);
    if (chunk < NEXP) atomicAdd(&g_ctotal[h], b2[chunk * HDIM + h]);
}

// ---------------- transpose weights -> K-major [E][N][K], bf16 ----------------
__global__ void transpose_w(const float* __restrict__ src, int which) {
    __shared__ float t[32][33];
    const int R = which ? FDIM : HDIM;      // src rows  (K)
    const int C = which ? HDIM : FDIM;      // src cols  (N, contiguous)
    __nv_bfloat16* dst = which ? g_w2t : g_w1t;
    const size_t base = (size_t)blockIdx.z * R * C;
    const int c0 = blockIdx.x * 32, r0 = blockIdx.y * 32;
    const int tx = threadIdx.x, ty = threadIdx.y;
    #pragma unroll
    for (int j = ty; j < 32; j += 8)
        t[j][tx] = src[base + (size_t)(r0 + j) * C + c0 + tx];
    __syncthreads();
    #pragma unroll
    for (int j = ty; j < 32; j += 8)
        dst[base + (size_t)(c0 + j) * R + r0 + tx] = __float2bfloat16_rn(t[tx][j]);
}

// ---------------- LayerNorm + router ----------------
__global__ void __launch_bounds__(256) ln_router_kernel(const float* __restrict__ x,
                                                        const float* __restrict__ gamma,
                                                        const float* __restrict__ beta,
                                                        const float* __restrict__ Wr,
                                                        const float* __restrict__ br) {
    const int t = blockIdx.x;
    const int tid = threadIdx.x;
    const int lane = tid & 31, wid = tid >> 5;

    const float4 xv = ((const float4*)(x + (size_t)t * HDIM))[tid];
    float s1 = xv.x + xv.y + xv.z + xv.w;
    float s2 = xv.x*xv.x + xv.y*xv.y + xv.z*xv.z + xv.w*xv.w;
    #pragma unroll
    for (int o = 16; o; o >>= 1) {
        s1 += __shfl_xor_sync(0xffffffffu, s1, o);
        s2 += __shfl_xor_sync(0xffffffffu, s2, o);
    }
    __shared__ float rs1[8], rs2[8], s_mu, s_rs;
    if (lane == 0) { rs1[wid] = s1; rs2[wid] = s2; }
    __syncthreads();
    if (wid == 0) {
        float a = (lane < 8) ? rs1[lane] : 0.f;
        float b = (lane < 8) ? rs2[lane] : 0.f;
        #pragma unroll
        for (int o = 4; o; o >>= 1) {
            a += __shfl_xor_sync(0xffffffffu, a, o);
            b += __shfl_xor_sync(0xffffffffu, b, o);
        }
        if (lane == 0) {
            float mu = a * (1.f / HDIM);
            float var = b * (1.f / HDIM) - mu * mu;
            s_mu = mu; s_rs = rsqrtf(var + 1e-5f);
        }
    }
    __syncthreads();
    const float mu = s_mu, rs = s_rs;

    const float4 g  = ((const float4*)gamma)[tid];
    const float4 be = ((const float4*)beta)[tid];
    float4 xn;
    xn.x = (xv.x - mu) * rs * g.x + be.x;
    xn.y = (xv.y - mu) * rs * g.y + be.y;
    xn.z = (xv.z - mu) * rs * g.z + be.z;
    xn.w = (xv.w - mu) * rs * g.w + be.w;

    float lg[NEXP];
    #pragma unroll
    for (int e = 0; e < NEXP; e++) lg[e] = 0.f;
    const int h0 = tid * 4;
    const float xns[4] = {xn.x, xn.y, xn.z, xn.w};
    #pragma unroll
    for (int j = 0; j < 4; j++) {
        const float4 w0 = ((const float4*)(Wr + (size_t)(h0 + j) * NEXP))[0];
        const float4 w1 = ((const float4*)(Wr + (size_t)(h0 + j) * NEXP))[1];
        lg[0] += xns[j]*w0.x; lg[1] += xns[j]*w0.y; lg[2] += xns[j]*w0.z; lg[3] += xns[j]*w0.w;
        lg[4] += xns[j]*w1.x; lg[5] += xns[j]*w1.y; lg[6] += xns[j]*w1.z; lg[7] += xns[j]*w1.w;
    }
    #pragma unroll
    for (int e = 0; e < NEXP; e++)
        #pragma unroll
        for (int o = 16; o; o >>= 1)
            lg[e] += __shfl_xor_sync(0xffffffffu, lg[e], o);

    __shared__ float lred[8][NEXP];
    if (lane == 0)
        #pragma unroll
        for (int e = 0; e < NEXP; e++) lred[wid][e] = lg[e];
    __syncthreads();

    if (tid == 0) {
        float L[NEXP];
        #pragma unroll
        for (int e = 0; e < NEXP; e++) {
            L[e] = br[e];
            #pragma unroll
            for (int w = 0; w < 8; w++) L[e] += lred[w][e];
        }
        float mx = L[0];
        #pragma unroll
        for (int e = 1; e < NEXP; e++) mx = fmaxf(mx, L[e]);
        float ex[NEXP], den = 0.f;
        #pragma unroll
        for (int e = 0; e < NEXP; e++) { ex[e] = __expf(L[e] - mx); den += ex[e]; }
        int i0 = 0;
        #pragma unroll
        for (int e = 1; e < NEXP; e++) if (L[e] > L[i0]) i0 = e;
        int i1 = (i0 == 0) ? 1 : 0;
        #pragma unroll
        for (int e = 0; e < NEXP; e++) if (e != i0 && L[e] > L[i1]) i1 = e;
        float inv = 1.f / den;
        float sc0 = ex[i0] * inv, sc1 = ex[i1] * inv;
        g_score[2*t] = sc0; g_score[2*t+1] = sc1;
        g_stot[t] = sc0 + sc1;
        int p0 = atomicAdd(&g_cnt[i0], 1); g_elist[i0 * TOK + p0] = 2*t;
        int p1 = atomicAdd(&g_cnt[i1], 1); g_elist[i1 * TOK + p1] = 2*t + 1;
    }

    __nv_bfloat162 h01 = __floats2bfloat162_rn(xn.x, xn.y);
    __nv_bfloat162 h23 = __floats2bfloat162_rn(xn.z, xn.w);
    uint2 pk = make_uint2(*(uint32_t*)&h01, *(uint32_t*)&h23);
    *(uint2*)(g_xn + (size_t)t * HDIM + tid * 4) = pk;
}

__global__ void offsets_kernel() {
    if (threadIdx.x == 0) {
        int s = 0;
        #pragma unroll
        for (int e = 0; e < NEXP; e++) { g_off[e] = s; s += g_cnt[e]; }
    }
}

// ---------------- bf16 mma.sync GEMM: 512 threads, 16 warps (2m x 8n), warp tile 64x32 ----------------
// MODE 1: g_h[off+row] = bf16( relu(xn@W1+b1) - relu(b1) )   K=1024, N=4096
// MODE 2: g_y[ent]     = score * (g_h @ W2)                  K=4096, N=1024
template <int MODE>
__global__ void __launch_bounds__(NTHR, 1) mm_gemm(const float* __restrict__ bias) {
    constexpr int KD  = (MODE == 1) ? HDIM : FDIM;
    constexpr int ND  = (MODE == 1) ? FDIM : HDIM;
    constexpr int NKT = KD / BK;

    const int e = blockIdx.z;
    const int cnt = g_cnt[e];
    const int mb0 = blockIdx.y * BM;
    if (mb0 >= cnt) return;
    const int nb = blockIdx.x * BN;
    const int off = g_off[e];

    extern __shared__ char dyn[];
    __shared__ int   s_rowoff[BM];
    __shared__ int   s_ent[BM];
    __shared__ float s_sc[BM];

    const int tid = threadIdx.x;
    const int lane = tid & 31, wid = tid >> 5;
    const uint32_t sbase = smem_u32(dyn);

    if (tid < BM) {
        int r = mb0 + tid;
        int rc = (r < cnt) ? r : (cnt - 1);
        int ent = g_elist[e * TOK + rc];
        if (MODE == 1) {
            s_rowoff[tid] = (ent >> 1) * HDIM;
        } else {
            s_rowoff[tid] = (off + rc) * FDIM;
            s_ent[tid] = ent;
            s_sc[tid]  = g_score[ent];
        }
    }
    __syncthreads();

    const __nv_bfloat16* Ag = (MODE == 1) ? g_xn : g_h;
    const __nv_bfloat16* Bg = ((MODE == 1) ? g_w1t : g_w2t) + (size_t)(e * ND + nb) * KD;

    // cp.async mapping (512 threads):
    //   A: thread -> row tid>>2 (0..127), one 16B chunk c = tid&3
    //   B: thread -> rows tid>>2 and (tid>>2)+128, chunk c = tid&3
    const int grow = tid >> 2;
    const int gc   = tid & 3;

    auto load_stage = [&](int kt) {
        const uint32_t sa = sbase + (kt % NS) * STAGE_BYTES;
        const int k0 = kt * BK;
        const uint32_t aswz = (grow >> 1) & 3;
        cp16(sa + grow * 64 + ((gc ^ aswz) << 4),
             Ag + (size_t)s_rowoff[grow] + k0 + gc * 8);
        const uint32_t sb = sa + A_BYTES;
        #pragma unroll
        for (int i = 0; i < 2; i++) {
            const int br = grow + i * 128;
            const uint32_t bswz = (br >> 1) & 3;
            cp16(sb + br * 64 + ((gc ^ bswz) << 4),
                 Bg + (size_t)br * KD + k0 + gc * 8);
        }
    };

    // warp layout: 2 (m) x 8 (n); warp tile 64 x 32
    const int wm = wid & 1, wn = wid >> 1;
    const int jj = lane >> 3, ii = lane & 7;
    const int rA  = (jj & 1) * 8 + ii;      // ldsm row within 16 (A)
    const int chA = jj >> 1;
    const int sxA = (rA >> 1) & 3;
    const int rB  = (jj >> 1) * 8 + ii;     // ldsm row within 16 (B)
    const int chB = jj & 1;
    const int sxB = (rB >> 1) & 3;

    float acc[4][4][4];
    #pragma unroll
    for (int i = 0; i < 4; i++)
        #pragma unroll
        for (int j = 0; j < 4; j++)
            #pragma unroll
            for (int c = 0; c < 4; c++) acc[i][j][c] = 0.f;

    load_stage(0); cp_commit();
    load_stage(1); cp_commit();
    load_stage(2); cp_commit();

    #pragma unroll 1
    for (int kt = 0; kt < NKT; kt++) {
        cp_wait<NS - 2>();
        __syncthreads();
        const int nl = kt + NS - 1;
        if (nl < NKT) load_stage(nl);
        cp_commit();

        const uint32_t sa = sbase + (kt % NS) * STAGE_BYTES;
        const uint32_t aw = sa + (wm * 64 + rA) * 64;
        const uint32_t bw = sa + A_BYTES + (wn * 32 + rB) * 64;
        #pragma unroll
        for (int ks = 0; ks < 2; ks++) {
            uint32_t af[4][4];
            #pragma unroll
            for (int mb = 0; mb < 4; mb++)
                ldsm4(af[mb], aw + mb * 1024 + (((2*ks + chA) ^ sxA) << 4));
            uint32_t bf[2][4];
            #pragma unroll
            for (int np = 0; np < 2; np++)
                ldsm4(bf[np], bw + np * 1024 + (((2*ks + chB) ^ sxB) << 4));
            #pragma unroll
            for (int mb = 0; mb < 4; mb++)
                #pragma unroll
                for (int np = 0; np < 2; np++) {
                    mma_bf16(acc[mb][np*2+0], af[mb], bf[np][0], bf[np][1]);
                    mma_bf16(acc[mb][np*2+1], af[mb], bf[np][2], bf[np][3]);
                }
        }
    }

    // ---------------- epilogue ----------------
    const int qr = lane >> 2;             // 0..7
    const int qc = (lane & 3) * 2;
    #pragma unroll
    for (int mb = 0; mb < 4; mb++) {
        #pragma unroll
        for (int half = 0; half < 2; half++) {
            const int rloc = wm * 64 + mb * 16 + qr + half * 8;
            if (mb0 + rloc >= cnt) continue;
            #pragma unroll
            for (int nblk = 0; nblk < 4; nblk++) {
                const int cg = nb + wn * 32 + nblk * 8 + qc;
                float v0 = acc[mb][nblk][half * 2 + 0];
                float v1 = acc[mb][nblk][half * 2 + 1];
                if (MODE == 1) {
                    const float2 bb = *(const float2*)(bias + e * FDIM + cg);
                    v0 = fmaxf(v0 + bb.x, 0.f) - fmaxf(bb.x, 0.f);
                    v1 = fmaxf(v1 + bb.y, 0.f) - fmaxf(bb.y, 0.f);
                    __nv_bfloat162 pk = __floats2bfloat162_rn(v0, v1);
                    *(uint32_t*)(g_h + (size_t)(off + mb0 + rloc) * FDIM + cg) = *(uint32_t*)&pk;
                } else {
                    const float s = s_sc[rloc];
                    *(float2*)(g_y + (size_t)s_ent[rloc] * HDIM + cg) = make_float2(s * v0, s * v1);
                }
            }
        }
    }
}

// ---------------- combine ----------------
__global__ void __launch_bounds__(256) combine_kernel(const float* __restrict__ x,
                                                      float* __restrict__ out) {
    const int t = blockIdx.x;
    const int tid = threadIdx.x;
    const float st = g_stot[t];
    const float4 xv = ((const float4*)(x + (size_t)t * HDIM))[tid];
    const float4 ct = ((const float4*)g_ctotal)[tid];
    const float4 y0 = ((const float4*)(g_y + (size_t)(2*t)     * HDIM))[tid];
    const float4 y1 = ((const float4*)(g_y + (size_t)(2*t + 1) * HDIM))[tid];
    float4 o;
    o.x = xv.x + st * ct.x + y0.x + y1.x;
    o.y = xv.y + st * ct.y + y0.y + y1.y;
    o.z = xv.z + st * ct.z + y0.z + y1.z;
    o.w = xv.w + st * ct.w + y0.w + y1.w;
    ((float4*)(out + (size_t)t * HDIM))[tid] = o;
}

// ---------------- launch ----------------
extern "C" void kernel_launch(void* const* d_in, const int* in_sizes, int n_in,
                              void* d_out, int out_size) {
    (void)in_sizes; (void)n_in; (void)out_size;
    const float* x     = (const float*)d_in[0];
    const float* gamma = (const float*)d_in[1];
    const float* beta  = (const float*)d_in[2];
    const float* Wr    = (const float*)d_in[3];
    const float* br    = (const float*)d_in[4];
    const float* W1    = (const float*)d_in[5];
    const float* b1    = (const float*)d_in[6];
    const float* W2    = (const float*)d_in[7];
    const float* b2    = (const float*)d_in[8];
    float* out = (float*)d_out;

    const int smem = NS * STAGE_BYTES;   // 98304 B
    cudaFuncSetAttribute(mm_gemm<1>, cudaFuncAttributeMaxDynamicSharedMemorySize, smem);
    cudaFuncSetAttribute(mm_gemm<2>, cudaFuncAttributeMaxDynamicSharedMemorySize, smem);

    zero_kernel<<<1, 1024>>>();
    ctotal_kernel<<<dim3(HDIM / 256, 64), 256>>>(W2, b1, b2);
    transpose_w<<<dim3(FDIM / 32, HDIM / 32, NEXP), dim3(32, 8)>>>(W1, 0);
    transpose_w<<<dim3(HDIM / 32, FDIM / 32, NEXP), dim3(32, 8)>>>(W2, 1);
    ln_router_kernel<<<TOK, 256>>>(x, gamma, beta, Wr, br);
    offsets_kernel<<<1, 32>>>();
    mm_gemm<1><<<dim3(FDIM / BN, (2 * TOK) / BM, NEXP), NTHR, smem>>>(b1);
    mm_gemm<2><<<dim3(HDIM / BN, (2 * TOK) / BM, NEXP), NTHR, smem>>>(nullptr);
    combine_kernel<<<TOK, 256>>>(x, out);
}

// round 8
// speedup vs baseline: 2.4492x; 1.1748x over previous
#include <cuda_runtime.h>
#include <cuda_bf16.h>
#include <cstdint>

#define TOK   16384
#define HDIM  1024
#define FDIM  4096
#define NEXP  8

#define BM 128
#define BN 256
#define BK 64
#define NS 3
#define A_BYTES     16384          // 128 rows x 128 B (64 bf16)
#define B_BYTES     32768          // 256 rows x 128 B
#define STAGE_BYTES 49152
#define NTHR 512

// ---------------- scratch (device globals; no runtime allocation) ----------------
__device__ __nv_bfloat16 g_xn [(size_t)TOK * HDIM];          //  34 MB
__device__ __nv_bfloat16 g_h  [(size_t)TOK * 2 * FDIM];      // 268 MB
__device__ float         g_y  [(size_t)TOK * 2 * HDIM];      // 134 MB
__device__ __nv_bfloat16 g_w1t[(size_t)NEXP * FDIM * HDIM];  //  67 MB  W1^T [e][f][h] K-major
__device__ __nv_bfloat16 g_w2t[(size_t)NEXP * HDIM * FDIM];  //  67 MB  W2^T [e][h][f] K-major
__device__ float g_ctotal[HDIM];
__device__ float g_score[TOK * 2];
__device__ float g_stot[TOK];
__device__ int   g_cnt[NEXP];
__device__ int   g_off[NEXP];
__device__ int   g_elist[NEXP * TOK];

// ---------------- helpers ----------------
__device__ __forceinline__ uint32_t smem_u32(const void* p) {
    uint32_t a;
    asm("{ .reg .u64 t; cvta.to.shared.u64 t, %1; cvt.u32.u64 %0, t; }" : "=r"(a) : "l"(p));
    return a;
}
__device__ __forceinline__ void cp16(uint32_t dst, const void* src) {
    asm volatile("cp.async.cg.shared.global [%0], [%1], 16;" :: "r"(dst), "l"(src));
}
__device__ __forceinline__ void cp_commit() { asm volatile("cp.async.commit_group;"); }
template <int N> __device__ __forceinline__ void cp_wait() {
    asm volatile("cp.async.wait_group %0;" :: "n"(N));
}
__device__ __forceinline__ void ldsm4(uint32_t (&r)[4], uint32_t addr) {
    asm volatile("ldmatrix.sync.aligned.m8n8.x4.shared.b16 {%0,%1,%2,%3}, [%4];"
                 : "=r"(r[0]), "=r"(r[1]), "=r"(r[2]), "=r"(r[3]) : "r"(addr));
}
__device__ __forceinline__ void mma_bf16(float (&d)[4], const uint32_t (&a)[4],
                                         uint32_t b0, uint32_t b1) {
    asm volatile(
        "mma.sync.aligned.m16n8k16.row.col.f32.bf16.bf16.f32 "
        "{%0,%1,%2,%3}, {%4,%5,%6,%7}, {%8,%9}, {%0,%1,%2,%3};"
        : "+f"(d[0]), "+f"(d[1]), "+f"(d[2]), "+f"(d[3])
        : "r"(a[0]), "r"(a[1]), "r"(a[2]), "r"(a[3]), "r"(b0), "r"(b1));
}

// ---------------- kernel 0 ----------------
__global__ void zero_kernel() {
    int i = threadIdx.x;
    if (i < NEXP) g_cnt[i] = 0;
    g_ctotal[i] = 0.f;
}

// ---------------- c_total (exact fp32) ----------------
__global__ void ctotal_kernel(const float* __restrict__ W2, const float* __restrict__ b1,
                              const float* __restrict__ b2) {
    int h = blockIdx.x * 256 + threadIdx.x;
    int chunk = blockIdx.y;
    float acc = 0.f;
    for (int i = 0; i < 512; i++) {
        int ef = chunk * 512 + i;
        float bb = b1[ef];
        if (bb > 0.f) acc += bb * W2[(size_t)ef * HDIM + h];
    }
    if (acc != 0.f) atomicAdd(&g_ctotal[h], acc);
    if (chunk < NEXP) atomicAdd(&g_ctotal[h], b2[chunk * HDIM + h]);
}

// ---------------- transpose weights -> K-major [E][N][K], bf16 ----------------
__global__ void transpose_w(const float* __restrict__ src, int which) {
    __shared__ float t[32][33];
    const int R = which ? FDIM : HDIM;      // src rows  (K)
    const int C = which ? HDIM : FDIM;      // src cols  (N, contiguous)
    __nv_bfloat16* dst = which ? g_w2t : g_w1t;
    const size_t base = (size_t)blockIdx.z * R * C;
    const int c0 = blockIdx.x * 32, r0 = blockIdx.y * 32;
    const int tx = threadIdx.x, ty = threadIdx.y;
    #pragma unroll
    for (int j = ty; j < 32; j += 8)
        t[j][tx] = src[base + (size_t)(r0 + j) * C + c0 + tx];
    __syncthreads();
    #pragma unroll
    for (int j = ty; j < 32; j += 8)
        dst[base + (size_t)(c0 + j) * R + r0 + tx] = __float2bfloat16_rn(t[tx][j]);
}

// ---------------- LayerNorm + router ----------------
__global__ void __launch_bounds__(256) ln_router_kernel(const float* __restrict__ x,
                                                        const float* __restrict__ gamma,
                                                        const float* __restrict__ beta,
                                                        const float* __restrict__ Wr,
                                                        const float* __restrict__ br) {
    const int t = blockIdx.x;
    const int tid = threadIdx.x;
    const int lane = tid & 31, wid = tid >> 5;

    const float4 xv = ((const float4*)(x + (size_t)t * HDIM))[tid];
    float s1 = xv.x + xv.y + xv.z + xv.w;
    float s2 = xv.x*xv.x + xv.y*xv.y + xv.z*xv.z + xv.w*xv.w;
    #pragma unroll
    for (int o = 16; o; o >>= 1) {
        s1 += __shfl_xor_sync(0xffffffffu, s1, o);
        s2 += __shfl_xor_sync(0xffffffffu, s2, o);
    }
    __shared__ float rs1[8], rs2[8], s_mu, s_rs;
    if (lane == 0) { rs1[wid] = s1; rs2[wid] = s2; }
    __syncthreads();
    if (wid == 0) {
        float a = (lane < 8) ? rs1[lane] : 0.f;
        float b = (lane < 8) ? rs2[lane] : 0.f;
        #pragma unroll
        for (int o = 4; o; o >>= 1) {
            a += __shfl_xor_sync(0xffffffffu, a, o);
            b += __shfl_xor_sync(0xffffffffu, b, o);
        }
        if (lane == 0) {
            float mu = a * (1.f / HDIM);
            float var = b * (1.f / HDIM) - mu * mu;
            s_mu = mu; s_rs = rsqrtf(var + 1e-5f);
        }
    }
    __syncthreads();
    const float mu = s_mu, rs = s_rs;

    const float4 g  = ((const float4*)gamma)[tid];
    const float4 be = ((const float4*)beta)[tid];
    float4 xn;
    xn.x = (xv.x - mu) * rs * g.x + be.x;
    xn.y = (xv.y - mu) * rs * g.y + be.y;
    xn.z = (xv.z - mu) * rs * g.z + be.z;
    xn.w = (xv.w - mu) * rs * g.w + be.w;

    float lg[NEXP];
    #pragma unroll
    for (int e = 0; e < NEXP; e++) lg[e] = 0.f;
    const int h0 = tid * 4;
    const float xns[4] = {xn.x, xn.y, xn.z, xn.w};
    #pragma unroll
    for (int j = 0; j < 4; j++) {
        const float4 w0 = ((const float4*)(Wr + (size_t)(h0 + j) * NEXP))[0];
        const float4 w1 = ((const float4*)(Wr + (size_t)(h0 + j) * NEXP))[1];
        lg[0] += xns[j]*w0.x; lg[1] += xns[j]*w0.y; lg[2] += xns[j]*w0.z; lg[3] += xns[j]*w0.w;
        lg[4] += xns[j]*w1.x; lg[5] += xns[j]*w1.y; lg[6] += xns[j]*w1.z; lg[7] += xns[j]*w1.w;
    }
    #pragma unroll
    for (int e = 0; e < NEXP; e++)
        #pragma unroll
        for (int o = 16; o; o >>= 1)
            lg[e] += __shfl_xor_sync(0xffffffffu, lg[e], o);

    __shared__ float lred[8][NEXP];
    if (lane == 0)
        #pragma unroll
        for (int e = 0; e < NEXP; e++) lred[wid][e] = lg[e];
    __syncthreads();

    if (tid == 0) {
        float L[NEXP];
        #pragma unroll
        for (int e = 0; e < NEXP; e++) {
            L[e] = br[e];
            #pragma unroll
            for (int w = 0; w < 8; w++) L[e] += lred[w][e];
        }
        float mx = L[0];
        #pragma unroll
        for (int e = 1; e < NEXP; e++) mx = fmaxf(mx, L[e]);
        float ex[NEXP], den = 0.f;
        #pragma unroll
        for (int e = 0; e < NEXP; e++) { ex[e] = __expf(L[e] - mx); den += ex[e]; }
        int i0 = 0;
        #pragma unroll
        for (int e = 1; e < NEXP; e++) if (L[e] > L[i0]) i0 = e;
        int i1 = (i0 == 0) ? 1 : 0;
        #pragma unroll
        for (int e = 0; e < NEXP; e++) if (e != i0 && L[e] > L[i1]) i1 = e;
        float inv = 1.f / den;
        float sc0 = ex[i0] * inv, sc1 = ex[i1] * inv;
        g_score[2*t] = sc0; g_score[2*t+1] = sc1;
        g_stot[t] = sc0 + sc1;
        int p0 = atomicAdd(&g_cnt[i0], 1); g_elist[i0 * TOK + p0] = 2*t;
        int p1 = atomicAdd(&g_cnt[i1], 1); g_elist[i1 * TOK + p1] = 2*t + 1;
    }

    __nv_bfloat162 h01 = __floats2bfloat162_rn(xn.x, xn.y);
    __nv_bfloat162 h23 = __floats2bfloat162_rn(xn.z, xn.w);
    uint2 pk = make_uint2(*(uint32_t*)&h01, *(uint32_t*)&h23);
    *(uint2*)(g_xn + (size_t)t * HDIM + tid * 4) = pk;
}

__global__ void offsets_kernel() {
    if (threadIdx.x == 0) {
        int s = 0;
        #pragma unroll
        for (int e = 0; e < NEXP; e++) { g_off[e] = s; s += g_cnt[e]; }
    }
}

// ---------------- bf16 mma.sync GEMM: BK=64, 512 threads, 16 warps (2m x 8n) ----------------
// smem rows are 128 B (8 x 16B chunks), swizzle: chunk ^= (row & 7)
// MODE 1: g_h[off+row] = bf16( relu(xn@W1+b1) - relu(b1) )   K=1024, N=4096
// MODE 2: g_y[ent]     = score * (g_h @ W2)                  K=4096, N=1024
template <int MODE>
__global__ void __launch_bounds__(NTHR, 1) mm_gemm(const float* __restrict__ bias) {
    constexpr int KD  = (MODE == 1) ? HDIM : FDIM;
    constexpr int ND  = (MODE == 1) ? FDIM : HDIM;
    constexpr int NKT = KD / BK;

    const int e = blockIdx.z;
    const int cnt = g_cnt[e];
    const int mb0 = blockIdx.y * BM;
    if (mb0 >= cnt) return;
    const int nb = blockIdx.x * BN;
    const int off = g_off[e];

    extern __shared__ char dyn[];
    __shared__ int   s_rowoff[BM];
    __shared__ int   s_ent[BM];
    __shared__ float s_sc[BM];

    const int tid = threadIdx.x;
    const int lane = tid & 31, wid = tid >> 5;
    const uint32_t sbase = smem_u32(dyn);

    if (tid < BM) {
        int r = mb0 + tid;
        int rc = (r < cnt) ? r : (cnt - 1);
        int ent = g_elist[e * TOK + rc];
        if (MODE == 1) {
            s_rowoff[tid] = (ent >> 1) * HDIM;
        } else {
            s_rowoff[tid] = (off + rc) * FDIM;
            s_ent[tid] = ent;
            s_sc[tid]  = g_score[ent];
        }
    }
    __syncthreads();

    const __nv_bfloat16* Ag = (MODE == 1) ? g_xn : g_h;
    const __nv_bfloat16* Bg = ((MODE == 1) ? g_w1t : g_w2t) + (size_t)(e * ND + nb) * KD;

    // cp.async mapping (512 threads, 128B rows, 8 chunks):
    //   row = tid>>3 (0..63), chunk = tid&7
    //   A: rows grow, grow+64                (2 cp16)
    //   B: rows grow, +64, +128, +192        (4 cp16)
    const int grow = tid >> 3;
    const int gc   = tid & 7;

    auto load_stage = [&](int kt) {
        const uint32_t sa = sbase + (kt % NS) * STAGE_BYTES;
        const int k0 = kt * BK;
        #pragma unroll
        for (int i = 0; i < 2; i++) {
            const int ar = grow + i * 64;
            cp16(sa + ar * 128 + ((gc ^ (ar & 7)) << 4),
                 Ag + (size_t)s_rowoff[ar] + k0 + gc * 8);
        }
        const uint32_t sb = sa + A_BYTES;
        #pragma unroll
        for (int i = 0; i < 4; i++) {
            const int br = grow + i * 64;
            cp16(sb + br * 128 + ((gc ^ (br & 7)) << 4),
                 Bg + (size_t)br * KD + k0 + gc * 8);
        }
    };

    // warp layout: 2 (m) x 8 (n); warp tile 64 x 32
    const int wm = wid & 1, wn = wid >> 1;
    const int jj = lane >> 3, ii = lane & 7;
    const int rA  = (jj & 1) * 8 + ii;      // ldsm row within 16 (A); (row&7)==ii
    const int chA = jj >> 1;
    const int rB  = (jj >> 1) * 8 + ii;     // ldsm row within 16 (B)
    const int chB = jj & 1;

    float acc[4][4][4];
    #pragma unroll
    for (int i = 0; i < 4; i++)
        #pragma unroll
        for (int j = 0; j < 4; j++)
            #pragma unroll
            for (int c = 0; c < 4; c++) acc[i][j][c] = 0.f;

    load_stage(0); cp_commit();
    load_stage(1); cp_commit();

    #pragma unroll 1
    for (int kt = 0; kt < NKT; kt++) {
        cp_wait<NS - 2>();
        __syncthreads();
        const int nl = kt + NS - 1;
        if (nl < NKT) load_stage(nl);
        cp_commit();

        const uint32_t sa = sbase + (kt % NS) * STAGE_BYTES;
        const uint32_t aw = sa + (wm * 64 + rA) * 128;
        const uint32_t bw = sa + A_BYTES + (wn * 32 + rB) * 128;
        const int sxA = ii;                  // (row & 7) for all A ldsm rows
        const int sxB = ii;
        #pragma unroll
        for (int ks = 0; ks < 4; ks++) {
            uint32_t af[4][4];
            #pragma unroll
            for (int mb = 0; mb < 4; mb++)
                ldsm4(af[mb], aw + mb * 2048 + (((2*ks + chA) ^ sxA) << 4));
            uint32_t bf[2][4];
            #pragma unroll
            for (int np = 0; np < 2; np++)
                ldsm4(bf[np], bw + np * 2048 + (((2*ks + chB) ^ sxB) << 4));
            #pragma unroll
            for (int mb = 0; mb < 4; mb++)
                #pragma unroll
                for (int np = 0; np < 2; np++) {
                    mma_bf16(acc[mb][np*2+0], af[mb], bf[np][0], bf[np][1]);
                    mma_bf16(acc[mb][np*2+1], af[mb], bf[np][2], bf[np][3]);
                }
        }
    }

    // ---------------- epilogue ----------------
    const int qr = lane >> 2;             // 0..7
    const int qc = (lane & 3) * 2;
    #pragma unroll
    for (int mb = 0; mb < 4; mb++) {
        #pragma unroll
        for (int half = 0; half < 2; half++) {
            const int rloc = wm * 64 + mb * 16 + qr + half * 8;
            if (mb0 + rloc >= cnt) continue;
            #pragma unroll
            for (int nblk = 0; nblk < 4; nblk++) {
                const int cg = nb + wn * 32 + nblk * 8 + qc;
                float v0 = acc[mb][nblk][half * 2 + 0];
                float v1 = acc[mb][nblk][half * 2 + 1];
                if (MODE == 1) {
                    const float2 bb = *(const float2*)(bias + e * FDIM + cg);
                    v0 = fmaxf(v0 + bb.x, 0.f) - fmaxf(bb.x, 0.f);
                    v1 = fmaxf(v1 + bb.y, 0.f) - fmaxf(bb.y, 0.f);
                    __nv_bfloat162 pk = __floats2bfloat162_rn(v0, v1);
                    *(uint32_t*)(g_h + (size_t)(off + mb0 + rloc) * FDIM + cg) = *(uint32_t*)&pk;
                } else {
                    const float s = s_sc[rloc];
                    *(float2*)(g_y + (size_t)s_ent[rloc] * HDIM + cg) = make_float2(s * v0, s * v1);
                }
            }
        }
    }
}

// ---------------- combine ----------------
__global__ void __launch_bounds__(256) combine_kernel(const float* __restrict__ x,
                                                      float* __restrict__ out) {
    const int t = blockIdx.x;
    const int tid = threadIdx.x;
    const float st = g_stot[t];
    const float4 xv = ((const float4*)(x + (size_t)t * HDIM))[tid];
    const float4 ct = ((const float4*)g_ctotal)[tid];
    const float4 y0 = ((const float4*)(g_y + (size_t)(2*t)     * HDIM))[tid];
    const float4 y1 = ((const float4*)(g_y + (size_t)(2*t + 1) * HDIM))[tid];
    float4 o;
    o.x = xv.x + st * ct.x + y0.x + y1.x;
    o.y = xv.y + st * ct.y + y0.y + y1.y;
    o.z = xv.z + st * ct.z + y0.z + y1.z;
    o.w = xv.w + st * ct.w + y0.w + y1.w;
    ((float4*)(out + (size_t)t * HDIM))[tid] = o;
}

// ---------------- launch ----------------
extern "C" void kernel_launch(void* const* d_in, const int* in_sizes, int n_in,
                              void* d_out, int out_size) {
    (void)in_sizes; (void)n_in; (void)out_size;
    const float* x     = (const float*)d_in[0];
    const float* gamma = (const float*)d_in[1];
    const float* beta  = (const float*)d_in[2];
    const float* Wr    = (const float*)d_in[3];
    const float* br    = (const float*)d_in[4];
    const float* W1    = (const float*)d_in[5];
    const float* b1    = (const float*)d_in[6];
    const float* W2    = (const float*)d_in[7];
    const float* b2    = (const float*)d_in[8];
    float* out = (float*)d_out;

    const int smem = NS * STAGE_BYTES;   // 147456 B
    cudaFuncSetAttribute(mm_gemm<1>, cudaFuncAttributeMaxDynamicSharedMemorySize, smem);
    cudaFuncSetAttribute(mm_gemm<2>, cudaFuncAttributeMaxDynamicSharedMemorySize, smem);

    zero_kernel<<<1, 1024>>>();
    ctotal_kernel<<<dim3(HDIM / 256, 64), 256>>>(W2, b1, b2);
    transpose_w<<<dim3(FDIM / 32, HDIM / 32, NEXP), dim3(32, 8)>>>(W1, 0);
    transpose_w<<<dim3(HDIM / 32, FDIM / 32, NEXP), dim3(32, 8)>>>(W2, 1);
    ln_router_kernel<<<TOK, 256>>>(x, gamma, beta, Wr, br);
    offsets_kernel<<<1, 32>>>();
    mm_gemm<1><<<dim3(FDIM / BN, (2 * TOK) / BM, NEXP), NTHR, smem>>>(b1);
    mm_gemm<2><<<dim3(HDIM / BN, (2 * TOK) / BM, NEXP), NTHR, smem>>>(nullptr);
    combine_kernel<<<TOK, 256>>>(x, out);
}

// round 9
// speedup vs baseline: 2.6732x; 1.0914x over previous
#include <cuda_runtime.h>
#include <cuda_bf16.h>
#include <cstdint>

#define TOK   16384
#define HDIM  1024
#define FDIM  4096
#define NEXP  8

#define BM 128
#define BN 256
#define BK 128
#define NS 2
#define A_BYTES     32768          // 128 rows x 256 B (128 bf16)
#define B_BYTES     65536          // 256 rows x 256 B
#define STAGE_BYTES 98304
#define NTHR 512

// ---------------- scratch (device globals; no runtime allocation) ----------------
__device__ __nv_bfloat16 g_xn [(size_t)TOK * HDIM];          //  34 MB
__device__ __nv_bfloat16 g_h  [(size_t)TOK * 2 * FDIM];      // 268 MB
__device__ float         g_y  [(size_t)TOK * 2 * HDIM];      // 134 MB
__device__ __nv_bfloat16 g_w1t[(size_t)NEXP * FDIM * HDIM];  //  67 MB  W1^T [e][f][h] K-major
__device__ __nv_bfloat16 g_w2t[(size_t)NEXP * HDIM * FDIM];  //  67 MB  W2^T [e][h][f] K-major
__device__ float g_ctotal[HDIM];
__device__ float g_score[TOK * 2];
__device__ float g_stot[TOK];
__device__ int   g_cnt[NEXP];
__device__ int   g_off[NEXP];
__device__ int   g_elist[NEXP * TOK];

// ---------------- helpers ----------------
__device__ __forceinline__ uint32_t smem_u32(const void* p) {
    uint32_t a;
    asm("{ .reg .u64 t; cvta.to.shared.u64 t, %1; cvt.u32.u64 %0, t; }" : "=r"(a) : "l"(p));
    return a;
}
__device__ __forceinline__ void cp16(uint32_t dst, const void* src) {
    asm volatile("cp.async.cg.shared.global [%0], [%1], 16;" :: "r"(dst), "l"(src));
}
__device__ __forceinline__ void cp_commit() { asm volatile("cp.async.commit_group;"); }
template <int N> __device__ __forceinline__ void cp_wait() {
    asm volatile("cp.async.wait_group %0;" :: "n"(N));
}
__device__ __forceinline__ void ldsm4(uint32_t (&r)[4], uint32_t addr) {
    asm volatile("ldmatrix.sync.aligned.m8n8.x4.shared.b16 {%0,%1,%2,%3}, [%4];"
                 : "=r"(r[0]), "=r"(r[1]), "=r"(r[2]), "=r"(r[3]) : "r"(addr));
}
__device__ __forceinline__ void mma_bf16(float (&d)[4], const uint32_t (&a)[4],
                                         uint32_t b0, uint32_t b1) {
    asm volatile(
        "mma.sync.aligned.m16n8k16.row.col.f32.bf16.bf16.f32 "
        "{%0,%1,%2,%3}, {%4,%5,%6,%7}, {%8,%9}, {%0,%1,%2,%3};"
        : "+f"(d[0]), "+f"(d[1]), "+f"(d[2]), "+f"(d[3])
        : "r"(a[0]), "r"(a[1]), "r"(a[2]), "r"(a[3]), "r"(b0), "r"(b1));
}

// ---------------- kernel 0 ----------------
__global__ void zero_kernel() {
    int i = threadIdx.x;
    if (i < NEXP) g_cnt[i] = 0;
    g_ctotal[i] = 0.f;
}

// ---------------- c_total (exact fp32) ----------------
__global__ void ctotal_kernel(const float* __restrict__ W2, const float* __restrict__ b1,
                              const float* __restrict__ b2) {
    int h = blockIdx.x * 256 + threadIdx.x;
    int chunk = blockIdx.y;
    float acc = 0.f;
    for (int i = 0; i < 512; i++) {
        int ef = chunk * 512 + i;
        float bb = b1[ef];
        if (bb > 0.f) acc += bb * W2[(size_t)ef * HDIM + h];
    }
    if (acc != 0.f) atomicAdd(&g_ctotal[h], acc);
    if (chunk < NEXP) atomicAdd(&g_ctotal[h], b2[chunk * HDIM + h]);
}

// ---------------- transpose weights -> K-major [E][N][K], bf16 ----------------
// tile: 64 K-rows x 32 N-cols; both read and write sides move 128-byte lines
__global__ void __launch_bounds__(256) transpose_w(const float* __restrict__ src, int which) {
    __shared__ float t[64][33];
    const int R = which ? FDIM : HDIM;      // K (src rows)
    const int C = which ? HDIM : FDIM;      // N (src cols, contiguous)
    __nv_bfloat16* dst = which ? g_w2t : g_w1t;
    const size_t base = (size_t)blockIdx.z * R * C;
    const int c0 = blockIdx.x * 32, r0 = blockIdx.y * 64;
    const int tid = threadIdx.x;
    const int tc = tid & 31, tr = tid >> 5;           // read: 8 rows/pass x 32 cols
    #pragma unroll
    for (int j = 0; j < 64; j += 8)
        t[tr + j][tc] = src[base + (size_t)(r0 + tr + j) * C + c0 + tc];
    __syncthreads();
    const int wk = tid & 63, wn = tid >> 6;           // write: 4 dst rows/pass x 64 k
    __nv_bfloat16* dbase = dst + base;
    #pragma unroll
    for (int j = 0; j < 32; j += 4)
        dbase[(size_t)(c0 + wn + j) * R + r0 + wk] = __float2bfloat16_rn(t[wk][wn + j]);
}

// ---------------- LayerNorm + router ----------------
__global__ void __launch_bounds__(256) ln_router_kernel(const float* __restrict__ x,
                                                        const float* __restrict__ gamma,
                                                        const float* __restrict__ beta,
                                                        const float* __restrict__ Wr,
                                                        const float* __restrict__ br) {
    const int t = blockIdx.x;
    const int tid = threadIdx.x;
    const int lane = tid & 31, wid = tid >> 5;

    const float4 xv = ((const float4*)(x + (size_t)t * HDIM))[tid];
    float s1 = xv.x + xv.y + xv.z + xv.w;
    float s2 = xv.x*xv.x + xv.y*xv.y + xv.z*xv.z + xv.w*xv.w;
    #pragma unroll
    for (int o = 16; o; o >>= 1) {
        s1 += __shfl_xor_sync(0xffffffffu, s1, o);
        s2 += __shfl_xor_sync(0xffffffffu, s2, o);
    }
    __shared__ float rs1[8], rs2[8], s_mu, s_rs;
    if (lane == 0) { rs1[wid] = s1; rs2[wid] = s2; }
    __syncthreads();
    if (wid == 0) {
        float a = (lane < 8) ? rs1[lane] : 0.f;
        float b = (lane < 8) ? rs2[lane] : 0.f;
        #pragma unroll
        for (int o = 4; o; o >>= 1) {
            a += __shfl_xor_sync(0xffffffffu, a, o);
            b += __shfl_xor_sync(0xffffffffu, b, o);
        }
        if (lane == 0) {
            float mu = a * (1.f / HDIM);
            float var = b * (1.f / HDIM) - mu * mu;
            s_mu = mu; s_rs = rsqrtf(var + 1e-5f);
        }
    }
    __syncthreads();
    const float mu = s_mu, rs = s_rs;

    const float4 g  = ((const float4*)gamma)[tid];
    const float4 be = ((const float4*)beta)[tid];
    float4 xn;
    xn.x = (xv.x - mu) * rs * g.x + be.x;
    xn.y = (xv.y - mu) * rs * g.y + be.y;
    xn.z = (xv.z - mu) * rs * g.z + be.z;
    xn.w = (xv.w - mu) * rs * g.w + be.w;

    float lg[NEXP];
    #pragma unroll
    for (int e = 0; e < NEXP; e++) lg[e] = 0.f;
    const int h0 = tid * 4;
    const float xns[4] = {xn.x, xn.y, xn.z, xn.w};
    #pragma unroll
    for (int j = 0; j < 4; j++) {
        const float4 w0 = ((const float4*)(Wr + (size_t)(h0 + j) * NEXP))[0];
        const float4 w1 = ((const float4*)(Wr + (size_t)(h0 + j) * NEXP))[1];
        lg[0] += xns[j]*w0.x; lg[1] += xns[j]*w0.y; lg[2] += xns[j]*w0.z; lg[3] += xns[j]*w0.w;
        lg[4] += xns[j]*w1.x; lg[5] += xns[j]*w1.y; lg[6] += xns[j]*w1.z; lg[7] += xns[j]*w1.w;
    }
    #pragma unroll
    for (int e = 0; e < NEXP; e++)
        #pragma unroll
        for (int o = 16; o; o >>= 1)
            lg[e] += __shfl_xor_sync(0xffffffffu, lg[e], o);

    __shared__ float lred[8][NEXP];
    if (lane == 0)
        #pragma unroll
        for (int e = 0; e < NEXP; e++) lred[wid][e] = lg[e];
    __syncthreads();

    if (tid == 0) {
        float L[NEXP];
        #pragma unroll
        for (int e = 0; e < NEXP; e++) {
            L[e] = br[e];
            #pragma unroll
            for (int w = 0; w < 8; w++) L[e] += lred[w][e];
        }
        float mx = L[0];
        #pragma unroll
        for (int e = 1; e < NEXP; e++) mx = fmaxf(mx, L[e]);
        float ex[NEXP], den = 0.f;
        #pragma unroll
        for (int e = 0; e < NEXP; e++) { ex[e] = __expf(L[e] - mx); den += ex[e]; }
        int i0 = 0;
        #pragma unroll
        for (int e = 1; e < NEXP; e++) if (L[e] > L[i0]) i0 = e;
        int i1 = (i0 == 0) ? 1 : 0;
        #pragma unroll
        for (int e = 0; e < NEXP; e++) if (e != i0 && L[e] > L[i1]) i1 = e;
        float inv = 1.f / den;
        float sc0 = ex[i0] * inv, sc1 = ex[i1] * inv;
        g_score[2*t] = sc0; g_score[2*t+1] = sc1;
        g_stot[t] = sc0 + sc1;
        int p0 = atomicAdd(&g_cnt[i0], 1); g_elist[i0 * TOK + p0] = 2*t;
        int p1 = atomicAdd(&g_cnt[i1], 1); g_elist[i1 * TOK + p1] = 2*t + 1;
    }

    __nv_bfloat162 h01 = __floats2bfloat162_rn(xn.x, xn.y);
    __nv_bfloat162 h23 = __floats2bfloat162_rn(xn.z, xn.w);
    uint2 pk = make_uint2(*(uint32_t*)&h01, *(uint32_t*)&h23);
    *(uint2*)(g_xn + (size_t)t * HDIM + tid * 4) = pk;
}

__global__ void offsets_kernel() {
    if (threadIdx.x == 0) {
        int s = 0;
        #pragma unroll
        for (int e = 0; e < NEXP; e++) { g_off[e] = s; s += g_cnt[e]; }
    }
}

// ---------------- bf16 mma.sync GEMM: BK=128, NS=2, 512 threads, 16 warps (2m x 8n) ----------------
// smem rows are 256 B (16 x 16B chunks), swizzle: chunk ^= (row & 7) (low 3 bits)
// MODE 1: g_h[off+row] = bf16( relu(xn@W1+b1) - relu(b1) )   K=1024, N=4096
// MODE 2: g_y[ent]     = score * (g_h @ W2)                  K=4096, N=1024
template <int MODE>
__global__ void __launch_bounds__(NTHR, 1) mm_gemm(const float* __restrict__ bias) {
    constexpr int KD  = (MODE == 1) ? HDIM : FDIM;
    constexpr int ND  = (MODE == 1) ? FDIM : HDIM;
    constexpr int NKT = KD / BK;

    const int e = blockIdx.z;
    const int cnt = g_cnt[e];
    const int mb0 = blockIdx.y * BM;
    if (mb0 >= cnt) return;
    const int nb = blockIdx.x * BN;
    const int off = g_off[e];

    extern __shared__ char dyn[];
    __shared__ int   s_rowoff[BM];
    __shared__ int   s_ent[BM];
    __shared__ float s_sc[BM];

    const int tid = threadIdx.x;
    const int lane = tid & 31, wid = tid >> 5;
    const uint32_t sbase = smem_u32(dyn);

    if (tid < BM) {
        int r = mb0 + tid;
        int rc = (r < cnt) ? r : (cnt - 1);
        int ent = g_elist[e * TOK + rc];
        if (MODE == 1) {
            s_rowoff[tid] = (ent >> 1) * HDIM;
        } else {
            s_rowoff[tid] = (off + rc) * FDIM;
            s_ent[tid] = ent;
            s_sc[tid]  = g_score[ent];
        }
    }
    __syncthreads();

    const __nv_bfloat16* Ag = (MODE == 1) ? g_xn : g_h;
    const __nv_bfloat16* Bg = ((MODE == 1) ? g_w1t : g_w2t) + (size_t)(e * ND + nb) * KD;

    // cp.async mapping (512 threads, 256B rows, 16 chunks):
    //   row = tid>>4 (0..31), chunk = tid&15
    //   A: rows grow+{0,32,64,96}            (4 cp16)
    //   B: rows grow+{0..224 step 32}        (8 cp16)
    const int grow = tid >> 4;
    const int gc   = tid & 15;

    auto load_stage = [&](int kt) {
        const uint32_t sa = sbase + (kt & 1) * STAGE_BYTES;
        const int k0 = kt * BK;
        #pragma unroll
        for (int i = 0; i < 4; i++) {
            const int ar = grow + i * 32;
            cp16(sa + ar * 256 + ((gc ^ (ar & 7)) << 4),
                 Ag + (size_t)s_rowoff[ar] + k0 + gc * 8);
        }
        const uint32_t sb = sa + A_BYTES;
        #pragma unroll
        for (int i = 0; i < 8; i++) {
            const int br = grow + i * 32;
            cp16(sb + br * 256 + ((gc ^ (br & 7)) << 4),
                 Bg + (size_t)br * KD + k0 + gc * 8);
        }
    };

    // warp layout: 2 (m) x 8 (n); warp tile 64 x 32
    const int wm = wid & 1, wn = wid >> 1;
    const int jj = lane >> 3, ii = lane & 7;
    const int rA  = (jj & 1) * 8 + ii;      // ldsm row within 16 (A); (row&7)==ii
    const int chA = jj >> 1;
    const int rB  = (jj >> 1) * 8 + ii;     // ldsm row within 16 (B)
    const int chB = jj & 1;

    float acc[4][4][4];
    #pragma unroll
    for (int i = 0; i < 4; i++)
        #pragma unroll
        for (int j = 0; j < 4; j++)
            #pragma unroll
            for (int c = 0; c < 4; c++) acc[i][j][c] = 0.f;

    load_stage(0); cp_commit();

    #pragma unroll 1
    for (int kt = 0; kt < NKT; kt++) {
        cp_wait<0>();
        __syncthreads();
        const int nl = kt + 1;
        if (nl < NKT) load_stage(nl);
        cp_commit();

        const uint32_t sa = sbase + (kt & 1) * STAGE_BYTES;
        const uint32_t aw = sa + (wm * 64 + rA) * 256;
        const uint32_t bw = sa + A_BYTES + (wn * 32 + rB) * 256;
        const int sxA = ii;                  // (row & 7) for all A ldsm rows
        const int sxB = ii;
        #pragma unroll
        for (int ks = 0; ks < 8; ks++) {
            uint32_t af[4][4];
            #pragma unroll
            for (int mb = 0; mb < 4; mb++)
                ldsm4(af[mb], aw + mb * 4096 + (((2*ks + chA) ^ sxA) << 4));
            uint32_t bf[2][4];
            #pragma unroll
            for (int np = 0; np < 2; np++)
                ldsm4(bf[np], bw + np * 4096 + (((2*ks + chB) ^ sxB) << 4));
            #pragma unroll
            for (int mb = 0; mb < 4; mb++)
                #pragma unroll
                for (int np = 0; np < 2; np++) {
                    mma_bf16(acc[mb][np*2+0], af[mb], bf[np][0], bf[np][1]);
                    mma_bf16(acc[mb][np*2+1], af[mb], bf[np][2], bf[np][3]);
                }
        }
    }

    // ---------------- epilogue ----------------
    const int qr = lane >> 2;             // 0..7
    const int qc = (lane & 3) * 2;
    #pragma unroll
    for (int mb = 0; mb < 4; mb++) {
        #pragma unroll
        for (int half = 0; half < 2; half++) {
            const int rloc = wm * 64 + mb * 16 + qr + half * 8;
            if (mb0 + rloc >= cnt) continue;
            #pragma unroll
            for (int nblk = 0; nblk < 4; nblk++) {
                const int cg = nb + wn * 32 + nblk * 8 + qc;
                float v0 = acc[mb][nblk][half * 2 + 0];
                float v1 = acc[mb][nblk][half * 2 + 1];
                if (MODE == 1) {
                    const float2 bb = *(const float2*)(bias + e * FDIM + cg);
                    v0 = fmaxf(v0 + bb.x, 0.f) - fmaxf(bb.x, 0.f);
                    v1 = fmaxf(v1 + bb.y, 0.f) - fmaxf(bb.y, 0.f);
                    __nv_bfloat162 pk = __floats2bfloat162_rn(v0, v1);
                    *(uint32_t*)(g_h + (size_t)(off + mb0 + rloc) * FDIM + cg) = *(uint32_t*)&pk;
                } else {
                    const float s = s_sc[rloc];
                    *(float2*)(g_y + (size_t)s_ent[rloc] * HDIM + cg) = make_float2(s * v0, s * v1);
                }
            }
        }
    }
}

// ---------------- combine ----------------
__global__ void __launch_bounds__(256) combine_kernel(const float* __restrict__ x,
                                                      float* __restrict__ out) {
    const int t = blockIdx.x;
    const int tid = threadIdx.x;
    const float st = g_stot[t];
    const float4 xv = ((const float4*)(x + (size_t)t * HDIM))[tid];
    const float4 ct = ((const float4*)g_ctotal)[tid];
    const float4 y0 = ((const float4*)(g_y + (size_t)(2*t)     * HDIM))[tid];
    const float4 y1 = ((const float4*)(g_y + (size_t)(2*t + 1) * HDIM))[tid];
    float4 o;
    o.x = xv.x + st * ct.x + y0.x + y1.x;
    o.y = xv.y + st * ct.y + y0.y + y1.y;
    o.z = xv.z + st * ct.z + y0.z + y1.z;
    o.w = xv.w + st * ct.w + y0.w + y1.w;
    ((float4*)(out + (size_t)t * HDIM))[tid] = o;
}

// ---------------- launch ----------------
extern "C" void kernel_launch(void* const* d_in, const int* in_sizes, int n_in,
                              void* d_out, int out_size) {
    (void)in_sizes; (void)n_in; (void)out_size;
    const float* x     = (const float*)d_in[0];
    const float* gamma = (const float*)d_in[1];
    const float* beta  = (const float*)d_in[2];
    const float* Wr    = (const float*)d_in[3];
    const float* br    = (const float*)d_in[4];
    const float* W1    = (const float*)d_in[5];
    const float* b1    = (const float*)d_in[6];
    const float* W2    = (const float*)d_in[7];
    const float* b2    = (const float*)d_in[8];
    float* out = (float*)d_out;

    const int smem = NS * STAGE_BYTES;   // 196608 B
    cudaFuncSetAttribute(mm_gemm<1>, cudaFuncAttributeMaxDynamicSharedMemorySize, smem);
    cudaFuncSetAttribute(mm_gemm<2>, cudaFuncAttributeMaxDynamicSharedMemorySize, smem);

    zero_kernel<<<1, 1024>>>();
    ctotal_kernel<<<dim3(HDIM / 256, 64), 256>>>(W2, b1, b2);
    transpose_w<<<dim3(FDIM / 32, HDIM / 64, NEXP), 256>>>(W1, 0);
    transpose_w<<<dim3(HDIM / 32, FDIM / 64, NEXP), 256>>>(W2, 1);
    ln_router_kernel<<<TOK, 256>>>(x, gamma, beta, Wr, br);
    offsets_kernel<<<1, 32>>>();
    mm_gemm<1><<<dim3(FDIM / BN, (2 * TOK) / BM, NEXP), NTHR, smem>>>(b1);
    mm_gemm<2><<<dim3(HDIM / BN, (2 * TOK) / BM, NEXP), NTHR, smem>>>(nullptr);
    combine_kernel<<<TOK, 256>>>(x, out);
}